// round 13
// baseline (speedup 1.0000x reference)
#include <cuda_runtime.h>
#include <cuda_fp16.h>
#include <math.h>
#include <stdint.h>

// Problem constants
#define B_   2
#define TX_  1024
#define TY_  4096
#define C_   768
#define H_   12
#define D_   64

// Scratch (device globals: no allocation allowed)
__device__ __half g_xh [B_ * TX_ * C_];      // x fp16
__device__ __half g_yh [B_ * TY_ * C_];      // y fp16
__device__ __half g_wqh[C_ * C_];            // Wq fp16
__device__ __half g_wkvh[C_ * 2 * C_];       // Wkv fp16
__device__ __half g_wph[C_ * C_];            // Wproj fp16
__device__ __half g_qh [B_ * TX_ * C_];      // rope(q) * 0.125, fp16
__device__ __half g_kh [B_ * TY_ * C_];      // rope(k), fp16
__device__ __half g_vh [B_ * TY_ * C_];      // v, fp16
__device__ __half g_oh [B_ * TX_ * C_];      // attention output, fp16

// ---------------------------------------------------------------------------
// mma / ldmatrix / cp.async helpers (sm_80-era, valid on base sm_103)
// ---------------------------------------------------------------------------
__device__ __forceinline__ void mma_f16(float* d, const uint32_t* a, const uint32_t* b) {
    asm volatile(
        "mma.sync.aligned.m16n8k16.row.col.f32.f16.f16.f32 "
        "{%0,%1,%2,%3}, {%4,%5,%6,%7}, {%8,%9}, {%0,%1,%2,%3};"
        : "+f"(d[0]), "+f"(d[1]), "+f"(d[2]), "+f"(d[3])
        : "r"(a[0]), "r"(a[1]), "r"(a[2]), "r"(a[3]), "r"(b[0]), "r"(b[1]));
}

__device__ __forceinline__ void ldsm_x4(uint32_t& r0, uint32_t& r1, uint32_t& r2,
                                        uint32_t& r3, uint32_t addr) {
    asm volatile("ldmatrix.sync.aligned.m8n8.x4.shared.b16 {%0,%1,%2,%3}, [%4];"
                 : "=r"(r0), "=r"(r1), "=r"(r2), "=r"(r3) : "r"(addr));
}

__device__ __forceinline__ void ldsm_x4_trans(uint32_t& r0, uint32_t& r1, uint32_t& r2,
                                              uint32_t& r3, uint32_t addr) {
    asm volatile("ldmatrix.sync.aligned.m8n8.x4.trans.shared.b16 {%0,%1,%2,%3}, [%4];"
                 : "=r"(r0), "=r"(r1), "=r"(r2), "=r"(r3) : "r"(addr));
}

__device__ __forceinline__ uint32_t h2pack(float a, float b) {
    __half2 h = __floats2half2_rn(a, b);
    return *(uint32_t*)&h;
}

__device__ __forceinline__ void cp16(uint32_t dst, const void* src) {
    asm volatile("cp.async.ca.shared.global [%0], [%1], 16;" :: "r"(dst), "l"(src));
}
__device__ __forceinline__ void cp_commit() {
    asm volatile("cp.async.commit_group;" ::: "memory");
}
__device__ __forceinline__ void cp_wait1() {
    asm volatile("cp.async.wait_group 1;" ::: "memory");
}
__device__ __forceinline__ void cp_wait0() {
    asm volatile("cp.async.wait_group 0;" ::: "memory");
}

// ---------------------------------------------------------------------------
// fp32 -> fp16 conversion prepass (n multiple of 4)
// ---------------------------------------------------------------------------
__global__ __launch_bounds__(256) void cvt_kernel(
    const float* __restrict__ src, __half* __restrict__ dst, int n)
{
    int i = (blockIdx.x * 256 + threadIdx.x) * 4;
    if (i < n) {
        float4 v = *(const float4*)&src[i];
        __half2* d = (__half2*)&dst[i];
        d[0] = __floats2half2_rn(v.x, v.y);
        d[1] = __floats2half2_rn(v.z, v.w);
    }
}

// ---------------------------------------------------------------------------
// Tensor-core fp16 GEMM, cp.async 2-stage pipeline, fused epilogue.
// out = A[M,K] @ W[K,N], fp16 in. Block tile 128x128, 256 threads.
// mode 0: fp32 output to out0 (width N).
// mode 1: RoPE(pos) + *0.125 -> fp16 to out0 (width N). (Q path)
// mode 2: cols [0,splitN): RoPE(pos) -> fp16 out0; cols [splitN,N): fp16 out1.
// ---------------------------------------------------------------------------
#define AROW 40
#define BROW 136
#define A_STAGE (128 * AROW)     // halfs
#define B_STAGE (32 * BROW)

__global__ __launch_bounds__(256, 1) void gemm_h(
    const __half* __restrict__ A, const __half* __restrict__ W,
    void* __restrict__ out0v, void* __restrict__ out1v,
    int N, int K, int splitN, int mode,
    const float* __restrict__ pos, const float* __restrict__ invf)
{
    __shared__ __align__(16) __half Ast[2][A_STAGE];
    __shared__ __align__(16) __half Bst[2][B_STAGE];
    __shared__ float spos[128];
    __shared__ float sif[32];

    const int tid = threadIdx.x;
    const int wid = tid >> 5, lane = tid & 31;
    const int g = lane >> 2, t = lane & 3;
    const int warp_m = (wid >> 1) * 32;
    const int warp_n = (wid & 1) * 64;
    const int bn = blockIdx.x * 128, bm = blockIdx.y * 128;

    if (mode != 0) {
        if (tid < 128) spos[tid] = pos[bm + tid];
        if (tid < 32) sif[tid] = invf[tid];
    }

    float acc[2][8][4];
#pragma unroll
    for (int mt = 0; mt < 2; mt++)
#pragma unroll
        for (int nt = 0; nt < 8; nt++)
#pragma unroll
            for (int e = 0; e < 4; e++) acc[mt][nt][e] = 0.f;

    const uint32_t a_base = (uint32_t)__cvta_generic_to_shared(&Ast[0][0]);
    const uint32_t b_base = (uint32_t)__cvta_generic_to_shared(&Bst[0][0]);

    // cp.async fill lane mapping (per stage: A 512 x 16B, B 512 x 16B)
    const int a_row0 = tid >> 1, a_seg0 = (tid & 1) * 2;       // 2 segs per thread, rows 0..127
    const int b_row0 = tid >> 4, b_seg0 = (tid & 15);          // B: idx scheme below

    // issue loads for chunk c into stage s
    auto issue = [&](int s, int k0) {
        const uint32_t abase_s = a_base + (uint32_t)s * (A_STAGE * 2);
        const uint32_t bbase_s = b_base + (uint32_t)s * (B_STAGE * 2);
        // A: 128 rows x 32 halfs = 4 segs/row; thread -> (row = tid>>1, segs {0,1}+ (tid&1)*2)
#pragma unroll
        for (int e = 0; e < 2; e++) {
            int seg = a_seg0 + e;
            cp16(abase_s + (uint32_t)(a_row0 * AROW + seg * 8) * 2,
                 A + (size_t)(bm + a_row0) * K + k0 + seg * 8);
        }
        // B: 32 rows x 128 halfs = 16 segs/row; 512 copies: idx = tid + i*256
#pragma unroll
        for (int i = 0; i < 2; i++) {
            int idx = tid + i * 256;
            int row = idx >> 4, seg = idx & 15;
            cp16(bbase_s + (uint32_t)(row * BROW + seg * 8) * 2,
                 W + (size_t)(k0 + row) * N + bn + seg * 8);
        }
        cp_commit();
    };

    const uint32_t a_frag0 = (uint32_t)(warp_m + (lane & 15)) * (AROW * 2)
                           + (uint32_t)(lane >> 4) * 16;
    const uint32_t b_frag0 = (uint32_t)(lane & 15) * (BROW * 2)
                           + (uint32_t)(warp_n + (lane >> 4) * 8) * 2;

    const int nch = K / 32;
    issue(0, 0);

    for (int c = 0; c < nch; c++) {
        if (c + 1 < nch) { issue((c + 1) & 1, (c + 1) * 32); cp_wait1(); }
        else cp_wait0();
        __syncthreads();

        const uint32_t a_addr = a_base + (uint32_t)(c & 1) * (A_STAGE * 2) + a_frag0;
        const uint32_t b_addr = b_base + (uint32_t)(c & 1) * (B_STAGE * 2) + b_frag0;

#pragma unroll
        for (int kk16 = 0; kk16 < 32; kk16 += 16) {
            uint32_t af[2][4];
            ldsm_x4(af[0][0], af[0][1], af[0][2], af[0][3], a_addr + kk16 * 2);
            ldsm_x4(af[1][0], af[1][1], af[1][2], af[1][3],
                    a_addr + 16 * (AROW * 2) + kk16 * 2);

            uint32_t bf[8][2];
#pragma unroll
            for (int p = 0; p < 4; p++) {
                ldsm_x4_trans(bf[2 * p][0], bf[2 * p][1], bf[2 * p + 1][0], bf[2 * p + 1][1],
                              b_addr + (uint32_t)kk16 * (BROW * 2) + (uint32_t)p * 32);
            }
#pragma unroll
            for (int nt = 0; nt < 8; nt++) {
#pragma unroll
                for (int mt = 0; mt < 2; mt++)
                    mma_f16(acc[mt][nt], af[mt], bf[nt]);
            }
        }
        __syncthreads();
    }

    if (mode == 0) {
        float* dst = (float*)out0v;
#pragma unroll
        for (int mt = 0; mt < 2; mt++) {
#pragma unroll
            for (int nt = 0; nt < 8; nt++) {
                int row = bm + warp_m + mt * 16 + g;
                int col = bn + warp_n + nt * 8 + t * 2;
                *(float2*)&dst[(size_t)row * N + col] =
                    make_float2(acc[mt][nt][0], acc[mt][nt][1]);
                *(float2*)&dst[(size_t)(row + 8) * N + col] =
                    make_float2(acc[mt][nt][2], acc[mt][nt][3]);
            }
        }
    } else {
        const bool is_v = (mode == 2) && (bn >= splitN);
        __half* dsth;
        int col0, stride;
        if (mode == 1)      { dsth = (__half*)out0v; col0 = bn; stride = N; }
        else if (!is_v)     { dsth = (__half*)out0v; col0 = bn; stride = splitN; }
        else                { dsth = (__half*)out1v; col0 = bn - splitN; stride = N - splitN; }
        const float scale = (mode == 1) ? 0.125f : 1.0f;

#pragma unroll
        for (int mt = 0; mt < 2; mt++) {
            const int r0 = warp_m + mt * 16 + g;
            const float p0 = spos[r0], p1 = spos[r0 + 8];
#pragma unroll
            for (int nt = 0; nt < 8; nt++) {
                int col = col0 + warp_n + nt * 8 + t * 2;
                float e0 = acc[mt][nt][0], o0 = acc[mt][nt][1];
                float e1 = acc[mt][nt][2], o1 = acc[mt][nt][3];
                if (!is_v) {
                    const float fr = sif[(col & 63) >> 1];
                    float s, cc;
                    sincosf(p0 * fr, &s, &cc);
                    float te = e0 * cc - o0 * s, to = o0 * cc + e0 * s;
                    sincosf(p1 * fr, &s, &cc);
                    float te1 = e1 * cc - o1 * s, to1 = o1 * cc + e1 * s;
                    e0 = te * scale; o0 = to * scale;
                    e1 = te1 * scale; o1 = to1 * scale;
                }
                *(__half2*)&dsth[(size_t)(bm + r0) * stride + col] = __floats2half2_rn(e0, o0);
                *(__half2*)&dsth[(size_t)(bm + r0 + 8) * stride + col] = __floats2half2_rn(e1, o1);
            }
        }
    }
}

// ---------------------------------------------------------------------------
// Banded flash-attention, fp16 tensor cores, fp32 accumulate + softmax.
// Block = (b, h, 128-query tile), 256 threads = 8 warps, warp handles m16.
// q/k/v pre-converted fp16; output written fp16 to g_oh.
// ---------------------------------------------------------------------------
#define QROW 72   // halfs per smem row (64 + 8 pad, 144B)

__global__ __launch_bounds__(256) void attn_tc(
    const float* __restrict__ xt_g, const float* __restrict__ yt_g,
    const int* __restrict__ p_dist, const int* __restrict__ p_mind)
{
    __shared__ __align__(16) __half Qh[128 * QROW];
    __shared__ __align__(16) __half Kh[64 * QROW];
    __shared__ __align__(16) __half Vh[64 * QROW];
    __shared__ float sxt[128], syt[64];
    __shared__ int s_lo, s_hi;

    const int b = blockIdx.z, h = blockIdx.y, q0 = blockIdx.x * 128;
    const int tid = threadIdx.x;
    const int wid = tid >> 5, lane = tid & 31;
    const int g = lane >> 2, t = lane & 3;
    const int warp_q = wid * 16;

    const float fdist = (float)p_dist[0];
    const float fmind = (float)p_mind[0];
    const float* yt = yt_g + (size_t)b * TY_;

    // Q tile: 128 x 64 halves, raw copy
    const __half* qbase = g_qh + ((size_t)(b * TX_ + q0)) * C_ + h * D_;
#pragma unroll
    for (int i = 0; i < 4; i++) {
        int idx = tid + i * 256;            // 0..1023 uint4s
        int row = idx >> 3, off = (idx & 7) * 8;
        *(uint4*)&Qh[row * QROW + off] = *(const uint4*)&qbase[(size_t)row * C_ + off];
    }
    if (tid < 128) sxt[tid] = xt_g[b * TX_ + q0 + tid];

    if (tid == 0) {
        float xlo = xt_g[b * TX_ + q0] - fmind - fdist;
        float xhi = xt_g[b * TX_ + q0 + 127] - fmind;
        int lo = 0, hi = TY_;
        while (lo < hi) { int m = (lo + hi) >> 1; if (yt[m] < xlo) lo = m + 1; else hi = m; }
        s_lo = lo;
        int lo2 = lo, hi2 = TY_;
        while (lo2 < hi2) { int m = (lo2 + hi2) >> 1; if (yt[m] <= xhi) lo2 = m + 1; else hi2 = m; }
        s_hi = lo2;
    }
    __syncthreads();

    const uint32_t qb = (uint32_t)__cvta_generic_to_shared(Qh);
    const uint32_t kb = (uint32_t)__cvta_generic_to_shared(Kh);
    const uint32_t vb = (uint32_t)__cvta_generic_to_shared(Vh);

    const uint32_t a_addr = qb + (uint32_t)(warp_q + (lane & 15)) * (QROW * 2)
                               + (uint32_t)(lane >> 4) * 16;
    const uint32_t key_off = ((lane >> 4) << 3) + (lane & 7);
    const uint32_t d_off = ((lane >> 3) & 1) << 3;
    const uint32_t k_addr = kb + key_off * (QROW * 2) + d_off * 2;
    const uint32_t v_addr = vb + (uint32_t)(lane & 15) * (QROW * 2)
                               + (uint32_t)(lane >> 4) * 16;

    float oacc[8][4];
#pragma unroll
    for (int j = 0; j < 8; j++)
#pragma unroll
        for (int e = 0; e < 4; e++) oacc[j][e] = 0.f;
    float m0 = -1e30f, m1 = -1e30f, l0 = 0.f, l1 = 0.f;

    const __half* kbase = g_kh + ((size_t)b * TY_) * C_ + h * D_;
    const __half* vbase = g_vh + ((size_t)b * TY_) * C_ + h * D_;

    const int kstart = s_lo & ~63;
    const int kend = s_hi;
    const float xti0 = sxt[warp_q + g] - fmind;
    const float xti1 = sxt[warp_q + g + 8] - fmind;

    for (int k0 = kstart; k0 < kend; k0 += 64) {
        __syncthreads();
        if (tid < 64) syt[tid] = yt[k0 + tid];
#pragma unroll
        for (int i = 0; i < 2; i++) {
            int idx = tid + i * 256;
            int row = idx >> 3, off = (idx & 7) * 8;
            size_t go = (size_t)(k0 + row) * C_ + off;
            *(uint4*)&Kh[row * QROW + off] = *(const uint4*)&kbase[go];
            *(uint4*)&Vh[row * QROW + off] = *(const uint4*)&vbase[go];
        }
        __syncthreads();

        // ---- S = Q K^T ----
        uint32_t af[4][4];
#pragma unroll
        for (int ks = 0; ks < 4; ks++)
            ldsm_x4(af[ks][0], af[ks][1], af[ks][2], af[ks][3], a_addr + ks * 32);

        float sacc[8][4];
#pragma unroll
        for (int j = 0; j < 8; j++)
#pragma unroll
            for (int e = 0; e < 4; e++) sacc[j][e] = 0.f;

#pragma unroll
        for (int ks = 0; ks < 4; ks++) {
#pragma unroll
            for (int p = 0; p < 4; p++) {
                uint32_t b0, b1, b2, b3;
                ldsm_x4(b0, b1, b2, b3, k_addr + (uint32_t)p * (16 * QROW * 2) + (uint32_t)ks * 32);
                uint32_t bf0[2] = {b0, b1}, bf1[2] = {b2, b3};
                mma_f16(sacc[2 * p], af[ks], bf0);
                mma_f16(sacc[2 * p + 1], af[ks], bf1);
            }
        }

        // ---- mask + online softmax ----
        float rmax0 = -1e30f, rmax1 = -1e30f;
#pragma unroll
        for (int j = 0; j < 8; j++) {
            float yt0 = syt[8 * j + 2 * t];
            float yt1 = syt[8 * j + 2 * t + 1];
            sacc[j][0] = (xti0 >= yt0 && xti0 <= yt0 + fdist) ? sacc[j][0] : -1e30f;
            sacc[j][1] = (xti0 >= yt1 && xti0 <= yt1 + fdist) ? sacc[j][1] : -1e30f;
            sacc[j][2] = (xti1 >= yt0 && xti1 <= yt0 + fdist) ? sacc[j][2] : -1e30f;
            sacc[j][3] = (xti1 >= yt1 && xti1 <= yt1 + fdist) ? sacc[j][3] : -1e30f;
            rmax0 = fmaxf(rmax0, fmaxf(sacc[j][0], sacc[j][1]));
            rmax1 = fmaxf(rmax1, fmaxf(sacc[j][2], sacc[j][3]));
        }
        rmax0 = fmaxf(rmax0, __shfl_xor_sync(0xffffffffu, rmax0, 1));
        rmax0 = fmaxf(rmax0, __shfl_xor_sync(0xffffffffu, rmax0, 2));
        rmax1 = fmaxf(rmax1, __shfl_xor_sync(0xffffffffu, rmax1, 1));
        rmax1 = fmaxf(rmax1, __shfl_xor_sync(0xffffffffu, rmax1, 2));

        const float mn0 = fmaxf(m0, rmax0);
        const float mn1 = fmaxf(m1, rmax1);
        const float alpha0 = __expf(m0 - mn0);
        const float alpha1 = __expf(m1 - mn1);
        m0 = mn0; m1 = mn1;

        float rs0 = 0.f, rs1 = 0.f;
#pragma unroll
        for (int j = 0; j < 8; j++) {
            float p0 = __expf(sacc[j][0] - mn0);
            float p1 = __expf(sacc[j][1] - mn0);
            float p2 = __expf(sacc[j][2] - mn1);
            float p3 = __expf(sacc[j][3] - mn1);
            sacc[j][0] = p0; sacc[j][1] = p1; sacc[j][2] = p2; sacc[j][3] = p3;
            rs0 += p0 + p1;
            rs1 += p2 + p3;
        }
        rs0 += __shfl_xor_sync(0xffffffffu, rs0, 1);
        rs0 += __shfl_xor_sync(0xffffffffu, rs0, 2);
        rs1 += __shfl_xor_sync(0xffffffffu, rs1, 1);
        rs1 += __shfl_xor_sync(0xffffffffu, rs1, 2);
        l0 = l0 * alpha0 + rs0;
        l1 = l1 * alpha1 + rs1;

#pragma unroll
        for (int j = 0; j < 8; j++) {
            oacc[j][0] *= alpha0; oacc[j][1] *= alpha0;
            oacc[j][2] *= alpha1; oacc[j][3] *= alpha1;
        }

        // ---- O += P @ V ----
#pragma unroll
        for (int ks = 0; ks < 4; ks++) {
            uint32_t pa[4];
            pa[0] = h2pack(sacc[2 * ks][0], sacc[2 * ks][1]);
            pa[1] = h2pack(sacc[2 * ks][2], sacc[2 * ks][3]);
            pa[2] = h2pack(sacc[2 * ks + 1][0], sacc[2 * ks + 1][1]);
            pa[3] = h2pack(sacc[2 * ks + 1][2], sacc[2 * ks + 1][3]);
#pragma unroll
            for (int p = 0; p < 4; p++) {
                uint32_t b0, b1, b2, b3;
                ldsm_x4_trans(b0, b1, b2, b3,
                              v_addr + (uint32_t)ks * (16 * QROW * 2) + (uint32_t)p * 32);
                uint32_t bf0[2] = {b0, b1}, bf1[2] = {b2, b3};
                mma_f16(oacc[2 * p], pa, bf0);
                mma_f16(oacc[2 * p + 1], pa, bf1);
            }
        }
    }

    // Epilogue: normalize, write fp16
    const float inv0 = 1.f / l0;
    const float inv1 = 1.f / l1;
    __half* ob = g_oh + ((size_t)(b * TX_ + q0 + warp_q)) * C_ + h * D_;
#pragma unroll
    for (int j = 0; j < 8; j++) {
        int col = 8 * j + 2 * t;
        *(__half2*)&ob[(size_t)g * C_ + col] =
            __floats2half2_rn(oacc[j][0] * inv0, oacc[j][1] * inv0);
        *(__half2*)&ob[(size_t)(g + 8) * C_ + col] =
            __floats2half2_rn(oacc[j][2] * inv1, oacc[j][3] * inv1);
    }
}

// ---------------------------------------------------------------------------
// Launch
// inputs: 0 x, 1 x_t, 2 y, 3 y_t, 4 dist, 5 min_dist, 6 Wq, 7 Wkv, 8 Wproj, 9 inv_freq
// ---------------------------------------------------------------------------
extern "C" void kernel_launch(void* const* d_in, const int* in_sizes, int n_in,
                              void* d_out, int out_size)
{
    const float* x        = (const float*)d_in[0];
    const float* x_t      = (const float*)d_in[1];
    const float* y        = (const float*)d_in[2];
    const float* y_t      = (const float*)d_in[3];
    const int*   dist     = (const int*)d_in[4];
    const int*   mind     = (const int*)d_in[5];
    const float* Wq       = (const float*)d_in[6];
    const float* Wkv      = (const float*)d_in[7];
    const float* Wproj    = (const float*)d_in[8];
    const float* inv_freq = (const float*)d_in[9];
    float* out = (float*)d_out;

    __half *xh, *yh, *wqh, *wkvh, *wph, *qh, *kh, *vh, *oh;
    cudaGetSymbolAddress((void**)&xh, g_xh);
    cudaGetSymbolAddress((void**)&yh, g_yh);
    cudaGetSymbolAddress((void**)&wqh, g_wqh);
    cudaGetSymbolAddress((void**)&wkvh, g_wkvh);
    cudaGetSymbolAddress((void**)&wph, g_wph);
    cudaGetSymbolAddress((void**)&qh, g_qh);
    cudaGetSymbolAddress((void**)&kh, g_kh);
    cudaGetSymbolAddress((void**)&vh, g_vh);
    cudaGetSymbolAddress((void**)&oh, g_oh);

    // fp16 prepass
    const int nx = B_ * TX_ * C_, ny = B_ * TY_ * C_;
    const int nwq = C_ * C_, nwkv = C_ * 2 * C_;
    cvt_kernel<<<(nx / 4 + 255) / 256, 256>>>(x, xh, nx);
    cvt_kernel<<<(ny / 4 + 255) / 256, 256>>>(y, yh, ny);
    cvt_kernel<<<(nwq / 4 + 255) / 256, 256>>>(Wq, wqh, nwq);
    cvt_kernel<<<(nwkv / 4 + 255) / 256, 256>>>(Wkv, wkvh, nwkv);
    cvt_kernel<<<(nwq / 4 + 255) / 256, 256>>>(Wproj, wph, nwq);

    // q = rope(x @ Wq) * 0.125 -> fp16
    gemm_h<<<dim3(C_ / 128, (B_ * TX_) / 128), 256>>>(
        xh, wqh, qh, nullptr, C_, C_, 0, 1, x_t, inv_freq);
    // kv = y @ Wkv; k = rope(kv[:,:768]) -> fp16, v = kv[:,768:] -> fp16
    gemm_h<<<dim3(2 * C_ / 128, (B_ * TY_) / 128), 256>>>(
        yh, wkvh, kh, vh, 2 * C_, C_, C_, 2, y_t, inv_freq);
    // banded flash attention (fp16 tensor cores, 128-query tiles)
    attn_tc<<<dim3(TX_ / 128, H_, B_), 256>>>(x_t, y_t, dist, mind);
    // final projection: out = o @ Wproj (fp32 out)
    gemm_h<<<dim3(C_ / 128, (B_ * TX_) / 128), 256>>>(
        oh, wph, out, nullptr, C_, C_, 0, 0, nullptr, nullptr);
}

// round 14
// speedup vs baseline: 1.3779x; 1.3779x over previous
#include <cuda_runtime.h>
#include <cuda_fp16.h>
#include <math.h>
#include <stdint.h>

// Problem constants
#define B_   2
#define TX_  1024
#define TY_  4096
#define C_   768
#define H_   12
#define D_   64

// Scratch (device globals: no allocation allowed)
__device__ __half g_qh[B_ * TX_ * C_];   // rope(q) * 0.125, fp16
__device__ __half g_kh[B_ * TY_ * C_];   // rope(k), fp16
__device__ __half g_vh[B_ * TY_ * C_];   // v, fp16
__device__ float  g_o [B_ * TX_ * C_];   // attention output, fp32

// ---------------------------------------------------------------------------
// mma / ldmatrix helpers (sm_80-era instructions, valid on base sm_103)
// ---------------------------------------------------------------------------
__device__ __forceinline__ void mma_f16(float* d, const uint32_t* a, const uint32_t* b) {
    asm volatile(
        "mma.sync.aligned.m16n8k16.row.col.f32.f16.f16.f32 "
        "{%0,%1,%2,%3}, {%4,%5,%6,%7}, {%8,%9}, {%0,%1,%2,%3};"
        : "+f"(d[0]), "+f"(d[1]), "+f"(d[2]), "+f"(d[3])
        : "r"(a[0]), "r"(a[1]), "r"(a[2]), "r"(a[3]), "r"(b[0]), "r"(b[1]));
}

__device__ __forceinline__ void ldsm_x4(uint32_t& r0, uint32_t& r1, uint32_t& r2,
                                        uint32_t& r3, uint32_t addr) {
    asm volatile("ldmatrix.sync.aligned.m8n8.x4.shared.b16 {%0,%1,%2,%3}, [%4];"
                 : "=r"(r0), "=r"(r1), "=r"(r2), "=r"(r3) : "r"(addr));
}

__device__ __forceinline__ void ldsm_x4_trans(uint32_t& r0, uint32_t& r1, uint32_t& r2,
                                              uint32_t& r3, uint32_t addr) {
    asm volatile("ldmatrix.sync.aligned.m8n8.x4.trans.shared.b16 {%0,%1,%2,%3}, [%4];"
                 : "=r"(r0), "=r"(r1), "=r"(r2), "=r"(r3) : "r"(addr));
}

__device__ __forceinline__ uint32_t h2pack(float a, float b) {
    __half2 h = __floats2half2_rn(a, b);
    return *(uint32_t*)&h;
}

// ---------------------------------------------------------------------------
// GEMM body (identical math to the 262us R11 kernel).
// out = A[M,K] @ W[K,N], fp32 in. Block tile 128x128, 256 threads.
// mode 0: fp32 output to out0 (width N).
// mode 1: RoPE(pos) + *0.125 -> fp16 to out0 (width N). (Q path)
// mode 2: cols [0,splitN): RoPE(pos) -> fp16 out0; cols [splitN,N): fp16 out1.
// ---------------------------------------------------------------------------
#define AROW 40
#define BROW 136

__device__ __forceinline__ void gemm_body(
    const float* __restrict__ A, const float* __restrict__ W,
    void* __restrict__ out0v, void* __restrict__ out1v,
    int N, int K, int splitN, int mode,
    const float* __restrict__ pos, const float* __restrict__ invf,
    int bn, int bm)
{
    __shared__ __half Asm[128 * AROW];  // [m][k]
    __shared__ __half Bsm[32 * BROW];   // [k][n]
    __shared__ float spos[128];
    __shared__ float sif[32];

    const int tid = threadIdx.x;
    const int wid = tid >> 5, lane = tid & 31;
    const int g = lane >> 2, t = lane & 3;
    const int warp_m = (wid >> 1) * 32;
    const int warp_n = (wid & 1) * 64;

    if (mode != 0) {
        if (tid < 128) spos[tid] = pos[bm + tid];
        if (tid < 32) sif[tid] = invf[tid];
    }

    float acc[2][8][4];
#pragma unroll
    for (int mt = 0; mt < 2; mt++)
#pragma unroll
        for (int nt = 0; nt < 8; nt++)
#pragma unroll
            for (int e = 0; e < 4; e++) acc[mt][nt][e] = 0.f;

    const uint32_t a_base = (uint32_t)__cvta_generic_to_shared(Asm);
    const uint32_t b_base = (uint32_t)__cvta_generic_to_shared(Bsm);

    const uint32_t a_addr0 = a_base + (uint32_t)(warp_m + (lane & 15)) * (AROW * 2)
                                    + (uint32_t)(lane >> 4) * 16;
    const uint32_t a_addr1 = a_addr0 + 16 * (AROW * 2);
    const uint32_t b_addr_base = b_base + (uint32_t)(lane & 15) * (BROW * 2)
                                        + (uint32_t)(warp_n + (lane >> 4) * 8) * 2;

    const int nch = K / 32;
    for (int c = 0; c < nch; c++) {
        const int k0 = c * 32;
        __syncthreads();

#pragma unroll
        for (int i = 0; i < 4; i++) {
            int idx = tid + i * 256;
            int row = idx >> 3, c4 = (idx & 7) * 4;
            float4 v = *(const float4*)&A[(size_t)(bm + row) * K + k0 + c4];
            __half2* dst = (__half2*)&Asm[row * AROW + c4];
            dst[0] = __floats2half2_rn(v.x, v.y);
            dst[1] = __floats2half2_rn(v.z, v.w);
        }
#pragma unroll
        for (int i = 0; i < 4; i++) {
            int idx = tid + i * 256;
            int kk = idx >> 5, n4 = (idx & 31) * 4;
            float4 v = *(const float4*)&W[(size_t)(k0 + kk) * N + bn + n4];
            __half2* dst = (__half2*)&Bsm[kk * BROW + n4];
            dst[0] = __floats2half2_rn(v.x, v.y);
            dst[1] = __floats2half2_rn(v.z, v.w);
        }
        __syncthreads();

#pragma unroll
        for (int kk16 = 0; kk16 < 32; kk16 += 16) {
            uint32_t af[2][4];
            ldsm_x4(af[0][0], af[0][1], af[0][2], af[0][3], a_addr0 + kk16 * 2);
            ldsm_x4(af[1][0], af[1][1], af[1][2], af[1][3], a_addr1 + kk16 * 2);

            uint32_t bf[8][2];
#pragma unroll
            for (int p = 0; p < 4; p++) {
                ldsm_x4_trans(bf[2 * p][0], bf[2 * p][1], bf[2 * p + 1][0], bf[2 * p + 1][1],
                              b_addr_base + (uint32_t)kk16 * (BROW * 2) + (uint32_t)p * 32);
            }
#pragma unroll
            for (int nt = 0; nt < 8; nt++) {
#pragma unroll
                for (int mt = 0; mt < 2; mt++)
                    mma_f16(acc[mt][nt], af[mt], bf[nt]);
            }
        }
    }

    if (mode == 0) {
        float* dst = (float*)out0v;
#pragma unroll
        for (int mt = 0; mt < 2; mt++) {
#pragma unroll
            for (int nt = 0; nt < 8; nt++) {
                int row = bm + warp_m + mt * 16 + g;
                int col = bn + warp_n + nt * 8 + t * 2;
                *(float2*)&dst[(size_t)row * N + col] =
                    make_float2(acc[mt][nt][0], acc[mt][nt][1]);
                *(float2*)&dst[(size_t)(row + 8) * N + col] =
                    make_float2(acc[mt][nt][2], acc[mt][nt][3]);
            }
        }
    } else {
        const bool is_v = (mode == 2) && (bn >= splitN);
        __half* dsth;
        int col0, stride;
        if (mode == 1)      { dsth = (__half*)out0v; col0 = bn; stride = N; }
        else if (!is_v)     { dsth = (__half*)out0v; col0 = bn; stride = splitN; }
        else                { dsth = (__half*)out1v; col0 = bn - splitN; stride = N - splitN; }
        const float scale = (mode == 1) ? 0.125f : 1.0f;

#pragma unroll
        for (int mt = 0; mt < 2; mt++) {
            const int r0 = warp_m + mt * 16 + g;
            const float p0 = spos[r0], p1 = spos[r0 + 8];
#pragma unroll
            for (int nt = 0; nt < 8; nt++) {
                int col = col0 + warp_n + nt * 8 + t * 2;
                float e0 = acc[mt][nt][0], o0 = acc[mt][nt][1];
                float e1 = acc[mt][nt][2], o1 = acc[mt][nt][3];
                if (!is_v) {
                    const float fr = sif[(col & 63) >> 1];
                    float s, cc;
                    sincosf(p0 * fr, &s, &cc);
                    float te = e0 * cc - o0 * s, to = o0 * cc + e0 * s;
                    sincosf(p1 * fr, &s, &cc);
                    float te1 = e1 * cc - o1 * s, to1 = o1 * cc + e1 * s;
                    e0 = te * scale; o0 = to * scale;
                    e1 = te1 * scale; o1 = to1 * scale;
                }
                *(__half2*)&dsth[(size_t)(bm + r0) * stride + col] = __floats2half2_rn(e0, o0);
                *(__half2*)&dsth[(size_t)(bm + r0 + 8) * stride + col] = __floats2half2_rn(e1, o1);
            }
        }
    }
}

// Fused Q + KV projection: blocks [0,768) = KV gemm tiles, [768,864) = Q tiles.
#define KV_BLOCKS (12 * 64)   // (2C/128) x (B*TY/128)
#define Q_BLOCKS  (6 * 16)    // (C/128)  x (B*TX/128)

__global__ __launch_bounds__(256, 1) void gemm_qkv(
    const float* __restrict__ x, const float* __restrict__ Wq,
    const float* __restrict__ y, const float* __restrict__ Wkv,
    __half* __restrict__ qh, __half* __restrict__ kh, __half* __restrict__ vh,
    const float* __restrict__ x_t, const float* __restrict__ y_t,
    const float* __restrict__ invf)
{
    const int bid = blockIdx.x;
    if (bid < KV_BLOCKS) {
        int bn = (bid % 12) * 128, bm = (bid / 12) * 128;
        gemm_body(y, Wkv, kh, vh, 2 * C_, C_, C_, 2, y_t, invf, bn, bm);
    } else {
        int r = bid - KV_BLOCKS;
        int bn = (r % 6) * 128, bm = (r / 6) * 128;
        gemm_body(x, Wq, qh, nullptr, C_, C_, 0, 1, x_t, invf, bn, bm);
    }
}

// Standalone gemm for the output projection (mode 0, fp32 out).
__global__ __launch_bounds__(256, 1) void gemm_proj(
    const float* __restrict__ A, const float* __restrict__ W,
    float* __restrict__ out, int N, int K)
{
    gemm_body(A, W, out, nullptr, N, K, 0, 0, nullptr, nullptr,
              blockIdx.x * 128, blockIdx.y * 128);
}

// ---------------------------------------------------------------------------
// Banded flash-attention, fp16 tensor cores, fp32 accumulate + softmax.
// Block = (b, h, 128-query tile), 256 threads = 8 warps, warp handles m16.
// (identical to the 262us R11 kernel)
// ---------------------------------------------------------------------------
#define QROW 72   // halfs per smem row (64 + 8 pad, 144B)

__global__ __launch_bounds__(256) void attn_tc(
    const float* __restrict__ xt_g, const float* __restrict__ yt_g,
    const int* __restrict__ p_dist, const int* __restrict__ p_mind)
{
    __shared__ __align__(16) __half Qh[128 * QROW];
    __shared__ __align__(16) __half Kh[64 * QROW];
    __shared__ __align__(16) __half Vh[64 * QROW];
    __shared__ float sxt[128], syt[64];
    __shared__ int s_lo, s_hi;

    const int b = blockIdx.z, h = blockIdx.y, q0 = blockIdx.x * 128;
    const int tid = threadIdx.x;
    const int wid = tid >> 5, lane = tid & 31;
    const int g = lane >> 2, t = lane & 3;
    const int warp_q = wid * 16;

    const float fdist = (float)p_dist[0];
    const float fmind = (float)p_mind[0];
    const float* yt = yt_g + (size_t)b * TY_;

    const __half* qbase = g_qh + ((size_t)(b * TX_ + q0)) * C_ + h * D_;
#pragma unroll
    for (int i = 0; i < 4; i++) {
        int idx = tid + i * 256;
        int row = idx >> 3, off = (idx & 7) * 8;
        *(uint4*)&Qh[row * QROW + off] = *(const uint4*)&qbase[(size_t)row * C_ + off];
    }
    if (tid < 128) sxt[tid] = xt_g[b * TX_ + q0 + tid];

    if (tid == 0) {
        float xlo = xt_g[b * TX_ + q0] - fmind - fdist;
        float xhi = xt_g[b * TX_ + q0 + 127] - fmind;
        int lo = 0, hi = TY_;
        while (lo < hi) { int m = (lo + hi) >> 1; if (yt[m] < xlo) lo = m + 1; else hi = m; }
        s_lo = lo;
        int lo2 = lo, hi2 = TY_;
        while (lo2 < hi2) { int m = (lo2 + hi2) >> 1; if (yt[m] <= xhi) lo2 = m + 1; else hi2 = m; }
        s_hi = lo2;
    }
    __syncthreads();

    const uint32_t qb = (uint32_t)__cvta_generic_to_shared(Qh);
    const uint32_t kb = (uint32_t)__cvta_generic_to_shared(Kh);
    const uint32_t vb = (uint32_t)__cvta_generic_to_shared(Vh);

    const uint32_t a_addr = qb + (uint32_t)(warp_q + (lane & 15)) * (QROW * 2)
                               + (uint32_t)(lane >> 4) * 16;
    const uint32_t key_off = ((lane >> 4) << 3) + (lane & 7);
    const uint32_t d_off = ((lane >> 3) & 1) << 3;
    const uint32_t k_addr = kb + key_off * (QROW * 2) + d_off * 2;
    const uint32_t v_addr = vb + (uint32_t)(lane & 15) * (QROW * 2)
                               + (uint32_t)(lane >> 4) * 16;

    float oacc[8][4];
#pragma unroll
    for (int j = 0; j < 8; j++)
#pragma unroll
        for (int e = 0; e < 4; e++) oacc[j][e] = 0.f;
    float m0 = -1e30f, m1 = -1e30f, l0 = 0.f, l1 = 0.f;

    const __half* kbase = g_kh + ((size_t)b * TY_) * C_ + h * D_;
    const __half* vbase = g_vh + ((size_t)b * TY_) * C_ + h * D_;

    const int kstart = s_lo & ~63;
    const int kend = s_hi;
    const float xti0 = sxt[warp_q + g] - fmind;
    const float xti1 = sxt[warp_q + g + 8] - fmind;

    for (int k0 = kstart; k0 < kend; k0 += 64) {
        __syncthreads();
        if (tid < 64) syt[tid] = yt[k0 + tid];
#pragma unroll
        for (int i = 0; i < 2; i++) {
            int idx = tid + i * 256;
            int row = idx >> 3, off = (idx & 7) * 8;
            size_t go = (size_t)(k0 + row) * C_ + off;
            *(uint4*)&Kh[row * QROW + off] = *(const uint4*)&kbase[go];
            *(uint4*)&Vh[row * QROW + off] = *(const uint4*)&vbase[go];
        }
        __syncthreads();

        // ---- S = Q K^T ----
        uint32_t af[4][4];
#pragma unroll
        for (int ks = 0; ks < 4; ks++)
            ldsm_x4(af[ks][0], af[ks][1], af[ks][2], af[ks][3], a_addr + ks * 32);

        float sacc[8][4];
#pragma unroll
        for (int j = 0; j < 8; j++)
#pragma unroll
            for (int e = 0; e < 4; e++) sacc[j][e] = 0.f;

#pragma unroll
        for (int ks = 0; ks < 4; ks++) {
#pragma unroll
            for (int p = 0; p < 4; p++) {
                uint32_t b0, b1, b2, b3;
                ldsm_x4(b0, b1, b2, b3, k_addr + (uint32_t)p * (16 * QROW * 2) + (uint32_t)ks * 32);
                uint32_t bf0[2] = {b0, b1}, bf1[2] = {b2, b3};
                mma_f16(sacc[2 * p], af[ks], bf0);
                mma_f16(sacc[2 * p + 1], af[ks], bf1);
            }
        }

        // ---- mask + online softmax ----
        float rmax0 = -1e30f, rmax1 = -1e30f;
#pragma unroll
        for (int j = 0; j < 8; j++) {
            float yt0 = syt[8 * j + 2 * t];
            float yt1 = syt[8 * j + 2 * t + 1];
            sacc[j][0] = (xti0 >= yt0 && xti0 <= yt0 + fdist) ? sacc[j][0] : -1e30f;
            sacc[j][1] = (xti0 >= yt1 && xti0 <= yt1 + fdist) ? sacc[j][1] : -1e30f;
            sacc[j][2] = (xti1 >= yt0 && xti1 <= yt0 + fdist) ? sacc[j][2] : -1e30f;
            sacc[j][3] = (xti1 >= yt1 && xti1 <= yt1 + fdist) ? sacc[j][3] : -1e30f;
            rmax0 = fmaxf(rmax0, fmaxf(sacc[j][0], sacc[j][1]));
            rmax1 = fmaxf(rmax1, fmaxf(sacc[j][2], sacc[j][3]));
        }
        rmax0 = fmaxf(rmax0, __shfl_xor_sync(0xffffffffu, rmax0, 1));
        rmax0 = fmaxf(rmax0, __shfl_xor_sync(0xffffffffu, rmax0, 2));
        rmax1 = fmaxf(rmax1, __shfl_xor_sync(0xffffffffu, rmax1, 1));
        rmax1 = fmaxf(rmax1, __shfl_xor_sync(0xffffffffu, rmax1, 2));

        const float mn0 = fmaxf(m0, rmax0);
        const float mn1 = fmaxf(m1, rmax1);
        const float alpha0 = __expf(m0 - mn0);
        const float alpha1 = __expf(m1 - mn1);
        m0 = mn0; m1 = mn1;

        float rs0 = 0.f, rs1 = 0.f;
#pragma unroll
        for (int j = 0; j < 8; j++) {
            float p0 = __expf(sacc[j][0] - mn0);
            float p1 = __expf(sacc[j][1] - mn0);
            float p2 = __expf(sacc[j][2] - mn1);
            float p3 = __expf(sacc[j][3] - mn1);
            sacc[j][0] = p0; sacc[j][1] = p1; sacc[j][2] = p2; sacc[j][3] = p3;
            rs0 += p0 + p1;
            rs1 += p2 + p3;
        }
        rs0 += __shfl_xor_sync(0xffffffffu, rs0, 1);
        rs0 += __shfl_xor_sync(0xffffffffu, rs0, 2);
        rs1 += __shfl_xor_sync(0xffffffffu, rs1, 1);
        rs1 += __shfl_xor_sync(0xffffffffu, rs1, 2);
        l0 = l0 * alpha0 + rs0;
        l1 = l1 * alpha1 + rs1;

#pragma unroll
        for (int j = 0; j < 8; j++) {
            oacc[j][0] *= alpha0; oacc[j][1] *= alpha0;
            oacc[j][2] *= alpha1; oacc[j][3] *= alpha1;
        }

        // ---- O += P @ V ----
#pragma unroll
        for (int ks = 0; ks < 4; ks++) {
            uint32_t pa[4];
            pa[0] = h2pack(sacc[2 * ks][0], sacc[2 * ks][1]);
            pa[1] = h2pack(sacc[2 * ks][2], sacc[2 * ks][3]);
            pa[2] = h2pack(sacc[2 * ks + 1][0], sacc[2 * ks + 1][1]);
            pa[3] = h2pack(sacc[2 * ks + 1][2], sacc[2 * ks + 1][3]);
#pragma unroll
            for (int p = 0; p < 4; p++) {
                uint32_t b0, b1, b2, b3;
                ldsm_x4_trans(b0, b1, b2, b3,
                              v_addr + (uint32_t)ks * (16 * QROW * 2) + (uint32_t)p * 32);
                uint32_t bf0[2] = {b0, b1}, bf1[2] = {b2, b3};
                mma_f16(oacc[2 * p], pa, bf0);
                mma_f16(oacc[2 * p + 1], pa, bf1);
            }
        }
    }

    // Epilogue: normalize, write fp32
    const float inv0 = 1.f / l0;
    const float inv1 = 1.f / l1;
    float* ob = g_o + ((size_t)(b * TX_ + q0 + warp_q)) * C_ + h * D_;
#pragma unroll
    for (int j = 0; j < 8; j++) {
        int col = 8 * j + 2 * t;
        *(float2*)&ob[(size_t)g * C_ + col] =
            make_float2(oacc[j][0] * inv0, oacc[j][1] * inv0);
        *(float2*)&ob[(size_t)(g + 8) * C_ + col] =
            make_float2(oacc[j][2] * inv1, oacc[j][3] * inv1);
    }
}

// ---------------------------------------------------------------------------
// Launch
// inputs: 0 x, 1 x_t, 2 y, 3 y_t, 4 dist, 5 min_dist, 6 Wq, 7 Wkv, 8 Wproj, 9 inv_freq
// ---------------------------------------------------------------------------
extern "C" void kernel_launch(void* const* d_in, const int* in_sizes, int n_in,
                              void* d_out, int out_size)
{
    const float* x        = (const float*)d_in[0];
    const float* x_t      = (const float*)d_in[1];
    const float* y        = (const float*)d_in[2];
    const float* y_t      = (const float*)d_in[3];
    const int*   dist     = (const int*)d_in[4];
    const int*   mind     = (const int*)d_in[5];
    const float* Wq       = (const float*)d_in[6];
    const float* Wkv      = (const float*)d_in[7];
    const float* Wproj    = (const float*)d_in[8];
    const float* inv_freq = (const float*)d_in[9];
    float* out = (float*)d_out;

    __half *qh_p, *kh_p, *vh_p;
    float *o_p;
    cudaGetSymbolAddress((void**)&qh_p, g_qh);
    cudaGetSymbolAddress((void**)&kh_p, g_kh);
    cudaGetSymbolAddress((void**)&vh_p, g_vh);
    cudaGetSymbolAddress((void**)&o_p, g_o);

    // fused: kv = y @ Wkv (rope k, split v) AND q = rope(x @ Wq) * 0.125
    gemm_qkv<<<KV_BLOCKS + Q_BLOCKS, 256>>>(
        x, Wq, y, Wkv, qh_p, kh_p, vh_p, x_t, y_t, inv_freq);
    // banded flash attention (fp16 tensor cores, 128-query tiles)
    attn_tc<<<dim3(TX_ / 128, H_, B_), 256>>>(x_t, y_t, dist, mind);
    // final projection: out = o @ Wproj (fp32 out)
    gemm_proj<<<dim3(C_ / 128, (B_ * TX_) / 128), 256>>>(o_p, Wproj, out, C_, C_);
}

// round 15
// speedup vs baseline: 1.5186x; 1.1022x over previous
#include <cuda_runtime.h>
#include <cuda_fp16.h>
#include <math.h>
#include <stdint.h>

// Problem constants
#define B_   2
#define TX_  1024
#define TY_  4096
#define C_   768
#define H_   12
#define D_   64

// Scratch (device globals: no allocation allowed)
__device__ __half g_qh[B_ * TX_ * C_];   // rope(q) * 0.125, fp16
__device__ __half g_kh[B_ * TY_ * C_];   // rope(k), fp16
__device__ __half g_vh[B_ * TY_ * C_];   // v, fp16
__device__ float  g_o [B_ * TX_ * C_];   // attention output, fp32

// ---------------------------------------------------------------------------
// mma / ldmatrix helpers (sm_80-era instructions, valid on base sm_103)
// ---------------------------------------------------------------------------
__device__ __forceinline__ void mma_f16(float* d, const uint32_t* a, const uint32_t* b) {
    asm volatile(
        "mma.sync.aligned.m16n8k16.row.col.f32.f16.f16.f32 "
        "{%0,%1,%2,%3}, {%4,%5,%6,%7}, {%8,%9}, {%0,%1,%2,%3};"
        : "+f"(d[0]), "+f"(d[1]), "+f"(d[2]), "+f"(d[3])
        : "r"(a[0]), "r"(a[1]), "r"(a[2]), "r"(a[3]), "r"(b[0]), "r"(b[1]));
}

__device__ __forceinline__ void ldsm_x4(uint32_t& r0, uint32_t& r1, uint32_t& r2,
                                        uint32_t& r3, uint32_t addr) {
    asm volatile("ldmatrix.sync.aligned.m8n8.x4.shared.b16 {%0,%1,%2,%3}, [%4];"
                 : "=r"(r0), "=r"(r1), "=r"(r2), "=r"(r3) : "r"(addr));
}

__device__ __forceinline__ void ldsm_x4_trans(uint32_t& r0, uint32_t& r1, uint32_t& r2,
                                              uint32_t& r3, uint32_t addr) {
    asm volatile("ldmatrix.sync.aligned.m8n8.x4.trans.shared.b16 {%0,%1,%2,%3}, [%4];"
                 : "=r"(r0), "=r"(r1), "=r"(r2), "=r"(r3) : "r"(addr));
}

__device__ __forceinline__ uint32_t h2pack(float a, float b) {
    __half2 h = __floats2half2_rn(a, b);
    return *(uint32_t*)&h;
}

// ---------------------------------------------------------------------------
// GEMM body with register-staged prefetch (math identical to R13).
// out = A[M,K] @ W[K,N], fp32 in. Block tile 128x128, 256 threads.
// mode 0: fp32 output to out0 (width N).
// mode 1: RoPE(pos) + *0.125 -> fp16 to out0 (width N). (Q path)
// mode 2: cols [0,splitN): RoPE(pos) -> fp16 out0; cols [splitN,N): fp16 out1.
// ---------------------------------------------------------------------------
#define AROW 40
#define BROW 136

__device__ __forceinline__ void gemm_body(
    const float* __restrict__ A, const float* __restrict__ W,
    void* __restrict__ out0v, void* __restrict__ out1v,
    int N, int K, int splitN, int mode,
    const float* __restrict__ pos, const float* __restrict__ invf,
    int bn, int bm)
{
    __shared__ __half Asm[128 * AROW];  // [m][k]
    __shared__ __half Bsm[32 * BROW];   // [k][n]
    __shared__ float spos[128];
    __shared__ float sif[32];

    const int tid = threadIdx.x;
    const int wid = tid >> 5, lane = tid & 31;
    const int g = lane >> 2, t = lane & 3;
    const int warp_m = (wid >> 1) * 32;
    const int warp_n = (wid & 1) * 64;

    if (mode != 0) {
        if (tid < 128) spos[tid] = pos[bm + tid];
        if (tid < 32) sif[tid] = invf[tid];
    }

    float acc[2][8][4];
#pragma unroll
    for (int mt = 0; mt < 2; mt++)
#pragma unroll
        for (int nt = 0; nt < 8; nt++)
#pragma unroll
            for (int e = 0; e < 4; e++) acc[mt][nt][e] = 0.f;

    const uint32_t a_base = (uint32_t)__cvta_generic_to_shared(Asm);
    const uint32_t b_base = (uint32_t)__cvta_generic_to_shared(Bsm);

    const uint32_t a_addr0 = a_base + (uint32_t)(warp_m + (lane & 15)) * (AROW * 2)
                                    + (uint32_t)(lane >> 4) * 16;
    const uint32_t a_addr1 = a_addr0 + 16 * (AROW * 2);
    const uint32_t b_addr_base = b_base + (uint32_t)(lane & 15) * (BROW * 2)
                                        + (uint32_t)(warp_n + (lane >> 4) * 8) * 2;

    // per-thread fill coordinates (4 float4s for A, 4 for B)
    const int a_row = tid >> 3, a_c4 = (tid & 7) * 4;         // +32 rows per i
    const int b_kk = tid >> 5, b_n4 = (tid & 31) * 4;         // +8 kk per i

    float4 pa[4], pb[4];

    // prefetch chunk 0
#pragma unroll
    for (int i = 0; i < 4; i++) {
        pa[i] = *(const float4*)&A[(size_t)(bm + a_row + i * 32) * K + a_c4];
        pb[i] = *(const float4*)&W[(size_t)(b_kk + i * 8) * N + bn + b_n4];
    }
    // store chunk 0
#pragma unroll
    for (int i = 0; i < 4; i++) {
        __half2* da = (__half2*)&Asm[(a_row + i * 32) * AROW + a_c4];
        da[0] = __floats2half2_rn(pa[i].x, pa[i].y);
        da[1] = __floats2half2_rn(pa[i].z, pa[i].w);
        __half2* db = (__half2*)&Bsm[(b_kk + i * 8) * BROW + b_n4];
        db[0] = __floats2half2_rn(pb[i].x, pb[i].y);
        db[1] = __floats2half2_rn(pb[i].z, pb[i].w);
    }
    __syncthreads();

    const int nch = K / 32;
    for (int c = 0; c < nch; c++) {
        // issue next chunk's global loads (overlap with MMAs below)
        if (c + 1 < nch) {
            const int k0 = (c + 1) * 32;
#pragma unroll
            for (int i = 0; i < 4; i++) {
                pa[i] = *(const float4*)&A[(size_t)(bm + a_row + i * 32) * K + k0 + a_c4];
                pb[i] = *(const float4*)&W[(size_t)(k0 + b_kk + i * 8) * N + bn + b_n4];
            }
        }

        // compute chunk c from smem
#pragma unroll
        for (int kk16 = 0; kk16 < 32; kk16 += 16) {
            uint32_t af[2][4];
            ldsm_x4(af[0][0], af[0][1], af[0][2], af[0][3], a_addr0 + kk16 * 2);
            ldsm_x4(af[1][0], af[1][1], af[1][2], af[1][3], a_addr1 + kk16 * 2);

            uint32_t bf[8][2];
#pragma unroll
            for (int p = 0; p < 4; p++) {
                ldsm_x4_trans(bf[2 * p][0], bf[2 * p][1], bf[2 * p + 1][0], bf[2 * p + 1][1],
                              b_addr_base + (uint32_t)kk16 * (BROW * 2) + (uint32_t)p * 32);
            }
#pragma unroll
            for (int nt = 0; nt < 8; nt++) {
#pragma unroll
                for (int mt = 0; mt < 2; mt++)
                    mma_f16(acc[mt][nt], af[mt], bf[nt]);
            }
        }
        __syncthreads();   // all readers done with smem

        if (c + 1 < nch) {
#pragma unroll
            for (int i = 0; i < 4; i++) {
                __half2* da = (__half2*)&Asm[(a_row + i * 32) * AROW + a_c4];
                da[0] = __floats2half2_rn(pa[i].x, pa[i].y);
                da[1] = __floats2half2_rn(pa[i].z, pa[i].w);
                __half2* db = (__half2*)&Bsm[(b_kk + i * 8) * BROW + b_n4];
                db[0] = __floats2half2_rn(pb[i].x, pb[i].y);
                db[1] = __floats2half2_rn(pb[i].z, pb[i].w);
            }
            __syncthreads();
        }
    }

    if (mode == 0) {
        float* dst = (float*)out0v;
#pragma unroll
        for (int mt = 0; mt < 2; mt++) {
#pragma unroll
            for (int nt = 0; nt < 8; nt++) {
                int row = bm + warp_m + mt * 16 + g;
                int col = bn + warp_n + nt * 8 + t * 2;
                *(float2*)&dst[(size_t)row * N + col] =
                    make_float2(acc[mt][nt][0], acc[mt][nt][1]);
                *(float2*)&dst[(size_t)(row + 8) * N + col] =
                    make_float2(acc[mt][nt][2], acc[mt][nt][3]);
            }
        }
    } else {
        const bool is_v = (mode == 2) && (bn >= splitN);
        __half* dsth;
        int col0, stride;
        if (mode == 1)      { dsth = (__half*)out0v; col0 = bn; stride = N; }
        else if (!is_v)     { dsth = (__half*)out0v; col0 = bn; stride = splitN; }
        else                { dsth = (__half*)out1v; col0 = bn - splitN; stride = N - splitN; }
        const float scale = (mode == 1) ? 0.125f : 1.0f;

#pragma unroll
        for (int mt = 0; mt < 2; mt++) {
            const int r0 = warp_m + mt * 16 + g;
            const float p0 = spos[r0], p1 = spos[r0 + 8];
#pragma unroll
            for (int nt = 0; nt < 8; nt++) {
                int col = col0 + warp_n + nt * 8 + t * 2;
                float e0 = acc[mt][nt][0], o0 = acc[mt][nt][1];
                float e1 = acc[mt][nt][2], o1 = acc[mt][nt][3];
                if (!is_v) {
                    const float fr = sif[(col & 63) >> 1];
                    float s, cc;
                    sincosf(p0 * fr, &s, &cc);
                    float te = e0 * cc - o0 * s, to = o0 * cc + e0 * s;
                    sincosf(p1 * fr, &s, &cc);
                    float te1 = e1 * cc - o1 * s, to1 = o1 * cc + e1 * s;
                    e0 = te * scale; o0 = to * scale;
                    e1 = te1 * scale; o1 = to1 * scale;
                }
                *(__half2*)&dsth[(size_t)(bm + r0) * stride + col] = __floats2half2_rn(e0, o0);
                *(__half2*)&dsth[(size_t)(bm + r0 + 8) * stride + col] = __floats2half2_rn(e1, o1);
            }
        }
    }
}

// Fused Q + KV projection: blocks [0,768) = KV gemm tiles, [768,864) = Q tiles.
#define KV_BLOCKS (12 * 64)   // (2C/128) x (B*TY/128)
#define Q_BLOCKS  (6 * 16)    // (C/128)  x (B*TX/128)

__global__ __launch_bounds__(256, 1) void gemm_qkv(
    const float* __restrict__ x, const float* __restrict__ Wq,
    const float* __restrict__ y, const float* __restrict__ Wkv,
    __half* __restrict__ qh, __half* __restrict__ kh, __half* __restrict__ vh,
    const float* __restrict__ x_t, const float* __restrict__ y_t,
    const float* __restrict__ invf)
{
    const int bid = blockIdx.x;
    if (bid < KV_BLOCKS) {
        int bn = (bid % 12) * 128, bm = (bid / 12) * 128;
        gemm_body(y, Wkv, kh, vh, 2 * C_, C_, C_, 2, y_t, invf, bn, bm);
    } else {
        int r = bid - KV_BLOCKS;
        int bn = (r % 6) * 128, bm = (r / 6) * 128;
        gemm_body(x, Wq, qh, nullptr, C_, C_, 0, 1, x_t, invf, bn, bm);
    }
}

// Standalone gemm for the output projection (mode 0, fp32 out).
__global__ __launch_bounds__(256, 1) void gemm_proj(
    const float* __restrict__ A, const float* __restrict__ W,
    float* __restrict__ out, int N, int K)
{
    gemm_body(A, W, out, nullptr, N, K, 0, 0, nullptr, nullptr,
              blockIdx.x * 128, blockIdx.y * 128);
}

// ---------------------------------------------------------------------------
// Banded flash-attention, fp16 tensor cores, fp32 accumulate + softmax.
// Block = (b, h, 128-query tile), 256 threads = 8 warps, warp handles m16.
// (identical to the 242us R13 kernel)
// ---------------------------------------------------------------------------
#define QROW 72   // halfs per smem row (64 + 8 pad, 144B)

__global__ __launch_bounds__(256) void attn_tc(
    const float* __restrict__ xt_g, const float* __restrict__ yt_g,
    const int* __restrict__ p_dist, const int* __restrict__ p_mind)
{
    __shared__ __align__(16) __half Qh[128 * QROW];
    __shared__ __align__(16) __half Kh[64 * QROW];
    __shared__ __align__(16) __half Vh[64 * QROW];
    __shared__ float sxt[128], syt[64];
    __shared__ int s_lo, s_hi;

    const int b = blockIdx.z, h = blockIdx.y, q0 = blockIdx.x * 128;
    const int tid = threadIdx.x;
    const int wid = tid >> 5, lane = tid & 31;
    const int g = lane >> 2, t = lane & 3;
    const int warp_q = wid * 16;

    const float fdist = (float)p_dist[0];
    const float fmind = (float)p_mind[0];
    const float* yt = yt_g + (size_t)b * TY_;

    const __half* qbase = g_qh + ((size_t)(b * TX_ + q0)) * C_ + h * D_;
#pragma unroll
    for (int i = 0; i < 4; i++) {
        int idx = tid + i * 256;
        int row = idx >> 3, off = (idx & 7) * 8;
        *(uint4*)&Qh[row * QROW + off] = *(const uint4*)&qbase[(size_t)row * C_ + off];
    }
    if (tid < 128) sxt[tid] = xt_g[b * TX_ + q0 + tid];

    if (tid == 0) {
        float xlo = xt_g[b * TX_ + q0] - fmind - fdist;
        float xhi = xt_g[b * TX_ + q0 + 127] - fmind;
        int lo = 0, hi = TY_;
        while (lo < hi) { int m = (lo + hi) >> 1; if (yt[m] < xlo) lo = m + 1; else hi = m; }
        s_lo = lo;
        int lo2 = lo, hi2 = TY_;
        while (lo2 < hi2) { int m = (lo2 + hi2) >> 1; if (yt[m] <= xhi) lo2 = m + 1; else hi2 = m; }
        s_hi = lo2;
    }
    __syncthreads();

    const uint32_t qb = (uint32_t)__cvta_generic_to_shared(Qh);
    const uint32_t kb = (uint32_t)__cvta_generic_to_shared(Kh);
    const uint32_t vb = (uint32_t)__cvta_generic_to_shared(Vh);

    const uint32_t a_addr = qb + (uint32_t)(warp_q + (lane & 15)) * (QROW * 2)
                               + (uint32_t)(lane >> 4) * 16;
    const uint32_t key_off = ((lane >> 4) << 3) + (lane & 7);
    const uint32_t d_off = ((lane >> 3) & 1) << 3;
    const uint32_t k_addr = kb + key_off * (QROW * 2) + d_off * 2;
    const uint32_t v_addr = vb + (uint32_t)(lane & 15) * (QROW * 2)
                               + (uint32_t)(lane >> 4) * 16;

    float oacc[8][4];
#pragma unroll
    for (int j = 0; j < 8; j++)
#pragma unroll
        for (int e = 0; e < 4; e++) oacc[j][e] = 0.f;
    float m0 = -1e30f, m1 = -1e30f, l0 = 0.f, l1 = 0.f;

    const __half* kbase = g_kh + ((size_t)b * TY_) * C_ + h * D_;
    const __half* vbase = g_vh + ((size_t)b * TY_) * C_ + h * D_;

    const int kstart = s_lo & ~63;
    const int kend = s_hi;
    const float xti0 = sxt[warp_q + g] - fmind;
    const float xti1 = sxt[warp_q + g + 8] - fmind;

    for (int k0 = kstart; k0 < kend; k0 += 64) {
        __syncthreads();
        if (tid < 64) syt[tid] = yt[k0 + tid];
#pragma unroll
        for (int i = 0; i < 2; i++) {
            int idx = tid + i * 256;
            int row = idx >> 3, off = (idx & 7) * 8;
            size_t go = (size_t)(k0 + row) * C_ + off;
            *(uint4*)&Kh[row * QROW + off] = *(const uint4*)&kbase[go];
            *(uint4*)&Vh[row * QROW + off] = *(const uint4*)&vbase[go];
        }
        __syncthreads();

        // ---- S = Q K^T ----
        uint32_t af[4][4];
#pragma unroll
        for (int ks = 0; ks < 4; ks++)
            ldsm_x4(af[ks][0], af[ks][1], af[ks][2], af[ks][3], a_addr + ks * 32);

        float sacc[8][4];
#pragma unroll
        for (int j = 0; j < 8; j++)
#pragma unroll
            for (int e = 0; e < 4; e++) sacc[j][e] = 0.f;

#pragma unroll
        for (int ks = 0; ks < 4; ks++) {
#pragma unroll
            for (int p = 0; p < 4; p++) {
                uint32_t b0, b1, b2, b3;
                ldsm_x4(b0, b1, b2, b3, k_addr + (uint32_t)p * (16 * QROW * 2) + (uint32_t)ks * 32);
                uint32_t bf0[2] = {b0, b1}, bf1[2] = {b2, b3};
                mma_f16(sacc[2 * p], af[ks], bf0);
                mma_f16(sacc[2 * p + 1], af[ks], bf1);
            }
        }

        // ---- mask + online softmax ----
        float rmax0 = -1e30f, rmax1 = -1e30f;
#pragma unroll
        for (int j = 0; j < 8; j++) {
            float yt0 = syt[8 * j + 2 * t];
            float yt1 = syt[8 * j + 2 * t + 1];
            sacc[j][0] = (xti0 >= yt0 && xti0 <= yt0 + fdist) ? sacc[j][0] : -1e30f;
            sacc[j][1] = (xti0 >= yt1 && xti0 <= yt1 + fdist) ? sacc[j][1] : -1e30f;
            sacc[j][2] = (xti1 >= yt0 && xti1 <= yt0 + fdist) ? sacc[j][2] : -1e30f;
            sacc[j][3] = (xti1 >= yt1 && xti1 <= yt1 + fdist) ? sacc[j][3] : -1e30f;
            rmax0 = fmaxf(rmax0, fmaxf(sacc[j][0], sacc[j][1]));
            rmax1 = fmaxf(rmax1, fmaxf(sacc[j][2], sacc[j][3]));
        }
        rmax0 = fmaxf(rmax0, __shfl_xor_sync(0xffffffffu, rmax0, 1));
        rmax0 = fmaxf(rmax0, __shfl_xor_sync(0xffffffffu, rmax0, 2));
        rmax1 = fmaxf(rmax1, __shfl_xor_sync(0xffffffffu, rmax1, 1));
        rmax1 = fmaxf(rmax1, __shfl_xor_sync(0xffffffffu, rmax1, 2));

        const float mn0 = fmaxf(m0, rmax0);
        const float mn1 = fmaxf(m1, rmax1);
        const float alpha0 = __expf(m0 - mn0);
        const float alpha1 = __expf(m1 - mn1);
        m0 = mn0; m1 = mn1;

        float rs0 = 0.f, rs1 = 0.f;
#pragma unroll
        for (int j = 0; j < 8; j++) {
            float p0 = __expf(sacc[j][0] - mn0);
            float p1 = __expf(sacc[j][1] - mn0);
            float p2 = __expf(sacc[j][2] - mn1);
            float p3 = __expf(sacc[j][3] - mn1);
            sacc[j][0] = p0; sacc[j][1] = p1; sacc[j][2] = p2; sacc[j][3] = p3;
            rs0 += p0 + p1;
            rs1 += p2 + p3;
        }
        rs0 += __shfl_xor_sync(0xffffffffu, rs0, 1);
        rs0 += __shfl_xor_sync(0xffffffffu, rs0, 2);
        rs1 += __shfl_xor_sync(0xffffffffu, rs1, 1);
        rs1 += __shfl_xor_sync(0xffffffffu, rs1, 2);
        l0 = l0 * alpha0 + rs0;
        l1 = l1 * alpha1 + rs1;

#pragma unroll
        for (int j = 0; j < 8; j++) {
            oacc[j][0] *= alpha0; oacc[j][1] *= alpha0;
            oacc[j][2] *= alpha1; oacc[j][3] *= alpha1;
        }

        // ---- O += P @ V ----
#pragma unroll
        for (int ks = 0; ks < 4; ks++) {
            uint32_t pa[4];
            pa[0] = h2pack(sacc[2 * ks][0], sacc[2 * ks][1]);
            pa[1] = h2pack(sacc[2 * ks][2], sacc[2 * ks][3]);
            pa[2] = h2pack(sacc[2 * ks + 1][0], sacc[2 * ks + 1][1]);
            pa[3] = h2pack(sacc[2 * ks + 1][2], sacc[2 * ks + 1][3]);
#pragma unroll
            for (int p = 0; p < 4; p++) {
                uint32_t b0, b1, b2, b3;
                ldsm_x4_trans(b0, b1, b2, b3,
                              v_addr + (uint32_t)ks * (16 * QROW * 2) + (uint32_t)p * 32);
                uint32_t bf0[2] = {b0, b1}, bf1[2] = {b2, b3};
                mma_f16(oacc[2 * p], pa, bf0);
                mma_f16(oacc[2 * p + 1], pa, bf1);
            }
        }
    }

    // Epilogue: normalize, write fp32
    const float inv0 = 1.f / l0;
    const float inv1 = 1.f / l1;
    float* ob = g_o + ((size_t)(b * TX_ + q0 + warp_q)) * C_ + h * D_;
#pragma unroll
    for (int j = 0; j < 8; j++) {
        int col = 8 * j + 2 * t;
        *(float2*)&ob[(size_t)g * C_ + col] =
            make_float2(oacc[j][0] * inv0, oacc[j][1] * inv0);
        *(float2*)&ob[(size_t)(g + 8) * C_ + col] =
            make_float2(oacc[j][2] * inv1, oacc[j][3] * inv1);
    }
}

// ---------------------------------------------------------------------------
// Launch
// inputs: 0 x, 1 x_t, 2 y, 3 y_t, 4 dist, 5 min_dist, 6 Wq, 7 Wkv, 8 Wproj, 9 inv_freq
// ---------------------------------------------------------------------------
extern "C" void kernel_launch(void* const* d_in, const int* in_sizes, int n_in,
                              void* d_out, int out_size)
{
    const float* x        = (const float*)d_in[0];
    const float* x_t      = (const float*)d_in[1];
    const float* y        = (const float*)d_in[2];
    const float* y_t      = (const float*)d_in[3];
    const int*   dist     = (const int*)d_in[4];
    const int*   mind     = (const int*)d_in[5];
    const float* Wq       = (const float*)d_in[6];
    const float* Wkv      = (const float*)d_in[7];
    const float* Wproj    = (const float*)d_in[8];
    const float* inv_freq = (const float*)d_in[9];
    float* out = (float*)d_out;

    __half *qh_p, *kh_p, *vh_p;
    float *o_p;
    cudaGetSymbolAddress((void**)&qh_p, g_qh);
    cudaGetSymbolAddress((void**)&kh_p, g_kh);
    cudaGetSymbolAddress((void**)&vh_p, g_vh);
    cudaGetSymbolAddress((void**)&o_p, g_o);

    // fused: kv = y @ Wkv (rope k, split v) AND q = rope(x @ Wq) * 0.125
    gemm_qkv<<<KV_BLOCKS + Q_BLOCKS, 256>>>(
        x, Wq, y, Wkv, qh_p, kh_p, vh_p, x_t, y_t, inv_freq);
    // banded flash attention (fp16 tensor cores, 128-query tiles)
    attn_tc<<<dim3(TX_ / 128, H_, B_), 256>>>(x_t, y_t, dist, mind);
    // final projection: out = o @ Wproj (fp32 out)
    gemm_proj<<<dim3(C_ / 128, (B_ * TX_) / 128), 256>>>(o_p, Wproj, out, C_, C_);
}

// round 16
// speedup vs baseline: 1.5947x; 1.0501x over previous
#include <cuda_runtime.h>
#include <cuda_fp16.h>
#include <math.h>
#include <stdint.h>

// Problem constants
#define B_   2
#define TX_  1024
#define TY_  4096
#define C_   768
#define H_   12
#define D_   64

// Scratch (device globals: no allocation allowed)
__device__ __half g_qh[B_ * TX_ * C_];   // rope(q) * 0.125, fp16
__device__ __half g_kh[B_ * TY_ * C_];   // rope(k), fp16
__device__ __half g_vh[B_ * TY_ * C_];   // v, fp16
__device__ float  g_o [B_ * TX_ * C_];   // attention output, fp32

// ---------------------------------------------------------------------------
// mma / ldmatrix helpers (sm_80-era instructions, valid on base sm_103)
// ---------------------------------------------------------------------------
__device__ __forceinline__ void mma_f16(float* d, const uint32_t* a, const uint32_t* b) {
    asm volatile(
        "mma.sync.aligned.m16n8k16.row.col.f32.f16.f16.f32 "
        "{%0,%1,%2,%3}, {%4,%5,%6,%7}, {%8,%9}, {%0,%1,%2,%3};"
        : "+f"(d[0]), "+f"(d[1]), "+f"(d[2]), "+f"(d[3])
        : "r"(a[0]), "r"(a[1]), "r"(a[2]), "r"(a[3]), "r"(b[0]), "r"(b[1]));
}

__device__ __forceinline__ void ldsm_x4(uint32_t& r0, uint32_t& r1, uint32_t& r2,
                                        uint32_t& r3, uint32_t addr) {
    asm volatile("ldmatrix.sync.aligned.m8n8.x4.shared.b16 {%0,%1,%2,%3}, [%4];"
                 : "=r"(r0), "=r"(r1), "=r"(r2), "=r"(r3) : "r"(addr));
}

__device__ __forceinline__ void ldsm_x4_trans(uint32_t& r0, uint32_t& r1, uint32_t& r2,
                                              uint32_t& r3, uint32_t addr) {
    asm volatile("ldmatrix.sync.aligned.m8n8.x4.trans.shared.b16 {%0,%1,%2,%3}, [%4];"
                 : "=r"(r0), "=r"(r1), "=r"(r2), "=r"(r3) : "r"(addr));
}

__device__ __forceinline__ uint32_t h2pack(float a, float b) {
    __half2 h = __floats2half2_rn(a, b);
    return *(uint32_t*)&h;
}

// ---------------------------------------------------------------------------
// GEMM body, block tile 128x64, 256 threads, 2 CTAs/SM target.
// 8 warps = 4m x 2n, warp tile 32x32. Register-staged prefetch.
// out = A[M,K] @ W[K,N], fp32 in.
// mode 0: fp32 output to out0 (width N).
// mode 1: RoPE(pos) + *0.125 -> fp16 to out0 (width N). (Q path)
// mode 2: cols [0,splitN): RoPE(pos) -> fp16 out0; cols [splitN,N): fp16 out1.
// ---------------------------------------------------------------------------
#define AROW 40
#define BROWS 72    // 64 + 8 pad

__device__ __forceinline__ void gemm_body(
    const float* __restrict__ A, const float* __restrict__ W,
    void* __restrict__ out0v, void* __restrict__ out1v,
    int N, int K, int splitN, int mode,
    const float* __restrict__ pos, const float* __restrict__ invf,
    int bn, int bm)
{
    __shared__ __half Asm[128 * AROW];   // [m][k]
    __shared__ __half Bsm[32 * BROWS];   // [k][n]
    __shared__ float spos[128];
    __shared__ float sif[32];

    const int tid = threadIdx.x;
    const int wid = tid >> 5, lane = tid & 31;
    const int g = lane >> 2, t = lane & 3;
    const int warp_m = (wid >> 1) * 32;   // 0,32,64,96
    const int warp_n = (wid & 1) * 32;    // 0,32

    if (mode != 0) {
        if (tid < 128) spos[tid] = pos[bm + tid];
        if (tid < 32) sif[tid] = invf[tid];
    }

    float acc[2][4][4];
#pragma unroll
    for (int mt = 0; mt < 2; mt++)
#pragma unroll
        for (int nt = 0; nt < 4; nt++)
#pragma unroll
            for (int e = 0; e < 4; e++) acc[mt][nt][e] = 0.f;

    const uint32_t a_base = (uint32_t)__cvta_generic_to_shared(Asm);
    const uint32_t b_base = (uint32_t)__cvta_generic_to_shared(Bsm);

    const uint32_t a_addr0 = a_base + (uint32_t)(warp_m + (lane & 15)) * (AROW * 2)
                                    + (uint32_t)(lane >> 4) * 16;
    const uint32_t a_addr1 = a_addr0 + 16 * (AROW * 2);
    const uint32_t b_addr_base = b_base + (uint32_t)(lane & 15) * (BROWS * 2)
                                        + (uint32_t)(warp_n + (lane >> 4) * 8) * 2;

    // per-thread fill coordinates: A 4 float4s, B 2 float4s
    const int a_row = tid >> 3, a_c4 = (tid & 7) * 4;     // +32 rows per i
    const int b_kk = tid >> 4, b_n4 = (tid & 15) * 4;     // +16 kk per i

    float4 pa[4], pb[2];

    // prefetch chunk 0
#pragma unroll
    for (int i = 0; i < 4; i++)
        pa[i] = *(const float4*)&A[(size_t)(bm + a_row + i * 32) * K + a_c4];
#pragma unroll
    for (int i = 0; i < 2; i++)
        pb[i] = *(const float4*)&W[(size_t)(b_kk + i * 16) * N + bn + b_n4];

    // store chunk 0
#pragma unroll
    for (int i = 0; i < 4; i++) {
        __half2* da = (__half2*)&Asm[(a_row + i * 32) * AROW + a_c4];
        da[0] = __floats2half2_rn(pa[i].x, pa[i].y);
        da[1] = __floats2half2_rn(pa[i].z, pa[i].w);
    }
#pragma unroll
    for (int i = 0; i < 2; i++) {
        __half2* db = (__half2*)&Bsm[(b_kk + i * 16) * BROWS + b_n4];
        db[0] = __floats2half2_rn(pb[i].x, pb[i].y);
        db[1] = __floats2half2_rn(pb[i].z, pb[i].w);
    }
    __syncthreads();

    const int nch = K / 32;
    for (int c = 0; c < nch; c++) {
        // issue next chunk's global loads (overlap with MMAs below)
        if (c + 1 < nch) {
            const int k0 = (c + 1) * 32;
#pragma unroll
            for (int i = 0; i < 4; i++)
                pa[i] = *(const float4*)&A[(size_t)(bm + a_row + i * 32) * K + k0 + a_c4];
#pragma unroll
            for (int i = 0; i < 2; i++)
                pb[i] = *(const float4*)&W[(size_t)(k0 + b_kk + i * 16) * N + bn + b_n4];
        }

        // compute chunk c from smem
#pragma unroll
        for (int kk16 = 0; kk16 < 32; kk16 += 16) {
            uint32_t af[2][4];
            ldsm_x4(af[0][0], af[0][1], af[0][2], af[0][3], a_addr0 + kk16 * 2);
            ldsm_x4(af[1][0], af[1][1], af[1][2], af[1][3], a_addr1 + kk16 * 2);

            uint32_t bf[4][2];
#pragma unroll
            for (int p = 0; p < 2; p++) {
                ldsm_x4_trans(bf[2 * p][0], bf[2 * p][1], bf[2 * p + 1][0], bf[2 * p + 1][1],
                              b_addr_base + (uint32_t)kk16 * (BROWS * 2) + (uint32_t)p * 32);
            }
#pragma unroll
            for (int nt = 0; nt < 4; nt++) {
#pragma unroll
                for (int mt = 0; mt < 2; mt++)
                    mma_f16(acc[mt][nt], af[mt], bf[nt]);
            }
        }
        __syncthreads();   // all readers done with smem

        if (c + 1 < nch) {
#pragma unroll
            for (int i = 0; i < 4; i++) {
                __half2* da = (__half2*)&Asm[(a_row + i * 32) * AROW + a_c4];
                da[0] = __floats2half2_rn(pa[i].x, pa[i].y);
                da[1] = __floats2half2_rn(pa[i].z, pa[i].w);
            }
#pragma unroll
            for (int i = 0; i < 2; i++) {
                __half2* db = (__half2*)&Bsm[(b_kk + i * 16) * BROWS + b_n4];
                db[0] = __floats2half2_rn(pb[i].x, pb[i].y);
                db[1] = __floats2half2_rn(pb[i].z, pb[i].w);
            }
            __syncthreads();
        }
    }

    if (mode == 0) {
        float* dst = (float*)out0v;
#pragma unroll
        for (int mt = 0; mt < 2; mt++) {
#pragma unroll
            for (int nt = 0; nt < 4; nt++) {
                int row = bm + warp_m + mt * 16 + g;
                int col = bn + warp_n + nt * 8 + t * 2;
                *(float2*)&dst[(size_t)row * N + col] =
                    make_float2(acc[mt][nt][0], acc[mt][nt][1]);
                *(float2*)&dst[(size_t)(row + 8) * N + col] =
                    make_float2(acc[mt][nt][2], acc[mt][nt][3]);
            }
        }
    } else {
        const bool is_v = (mode == 2) && (bn >= splitN);
        __half* dsth;
        int col0, stride;
        if (mode == 1)      { dsth = (__half*)out0v; col0 = bn; stride = N; }
        else if (!is_v)     { dsth = (__half*)out0v; col0 = bn; stride = splitN; }
        else                { dsth = (__half*)out1v; col0 = bn - splitN; stride = N - splitN; }
        const float scale = (mode == 1) ? 0.125f : 1.0f;

#pragma unroll
        for (int mt = 0; mt < 2; mt++) {
            const int r0 = warp_m + mt * 16 + g;
            const float p0 = spos[r0], p1 = spos[r0 + 8];
#pragma unroll
            for (int nt = 0; nt < 4; nt++) {
                int col = col0 + warp_n + nt * 8 + t * 2;
                float e0 = acc[mt][nt][0], o0 = acc[mt][nt][1];
                float e1 = acc[mt][nt][2], o1 = acc[mt][nt][3];
                if (!is_v) {
                    const float fr = sif[(col & 63) >> 1];
                    float s, cc;
                    sincosf(p0 * fr, &s, &cc);
                    float te = e0 * cc - o0 * s, to = o0 * cc + e0 * s;
                    sincosf(p1 * fr, &s, &cc);
                    float te1 = e1 * cc - o1 * s, to1 = o1 * cc + e1 * s;
                    e0 = te * scale; o0 = to * scale;
                    e1 = te1 * scale; o1 = to1 * scale;
                }
                *(__half2*)&dsth[(size_t)(bm + r0) * stride + col] = __floats2half2_rn(e0, o0);
                *(__half2*)&dsth[(size_t)(bm + r0 + 8) * stride + col] = __floats2half2_rn(e1, o1);
            }
        }
    }
}

// Fused Q + KV projection with 128x64 tiles:
// KV: 24 N-tiles x 64 M-tiles = 1536 blocks; Q: 12 x 16 = 192 blocks.
#define KV_BLOCKS (24 * 64)
#define Q_BLOCKS  (12 * 16)

__global__ __launch_bounds__(256, 2) void gemm_qkv(
    const float* __restrict__ x, const float* __restrict__ Wq,
    const float* __restrict__ y, const float* __restrict__ Wkv,
    __half* __restrict__ qh, __half* __restrict__ kh, __half* __restrict__ vh,
    const float* __restrict__ x_t, const float* __restrict__ y_t,
    const float* __restrict__ invf)
{
    const int bid = blockIdx.x;
    if (bid < KV_BLOCKS) {
        int bn = (bid % 24) * 64, bm = (bid / 24) * 128;
        gemm_body(y, Wkv, kh, vh, 2 * C_, C_, C_, 2, y_t, invf, bn, bm);
    } else {
        int r = bid - KV_BLOCKS;
        int bn = (r % 12) * 64, bm = (r / 12) * 128;
        gemm_body(x, Wq, qh, nullptr, C_, C_, 0, 1, x_t, invf, bn, bm);
    }
}

// Standalone gemm for the output projection (mode 0, fp32 out).
__global__ __launch_bounds__(256, 2) void gemm_proj(
    const float* __restrict__ A, const float* __restrict__ W,
    float* __restrict__ out, int N, int K)
{
    gemm_body(A, W, out, nullptr, N, K, 0, 0, nullptr, nullptr,
              blockIdx.x * 64, blockIdx.y * 128);
}

// ---------------------------------------------------------------------------
// Banded flash-attention, fp16 tensor cores, fp32 accumulate + softmax.
// Block = (b, h, 128-query tile), 256 threads = 8 warps, warp handles m16.
// (identical to the 219.9us R14 kernel)
// ---------------------------------------------------------------------------
#define QROW 72   // halfs per smem row (64 + 8 pad, 144B)

__global__ __launch_bounds__(256) void attn_tc(
    const float* __restrict__ xt_g, const float* __restrict__ yt_g,
    const int* __restrict__ p_dist, const int* __restrict__ p_mind)
{
    __shared__ __align__(16) __half Qh[128 * QROW];
    __shared__ __align__(16) __half Kh[64 * QROW];
    __shared__ __align__(16) __half Vh[64 * QROW];
    __shared__ float sxt[128], syt[64];
    __shared__ int s_lo, s_hi;

    const int b = blockIdx.z, h = blockIdx.y, q0 = blockIdx.x * 128;
    const int tid = threadIdx.x;
    const int wid = tid >> 5, lane = tid & 31;
    const int g = lane >> 2, t = lane & 3;
    const int warp_q = wid * 16;

    const float fdist = (float)p_dist[0];
    const float fmind = (float)p_mind[0];
    const float* yt = yt_g + (size_t)b * TY_;

    const __half* qbase = g_qh + ((size_t)(b * TX_ + q0)) * C_ + h * D_;
#pragma unroll
    for (int i = 0; i < 4; i++) {
        int idx = tid + i * 256;
        int row = idx >> 3, off = (idx & 7) * 8;
        *(uint4*)&Qh[row * QROW + off] = *(const uint4*)&qbase[(size_t)row * C_ + off];
    }
    if (tid < 128) sxt[tid] = xt_g[b * TX_ + q0 + tid];

    if (tid == 0) {
        float xlo = xt_g[b * TX_ + q0] - fmind - fdist;
        float xhi = xt_g[b * TX_ + q0 + 127] - fmind;
        int lo = 0, hi = TY_;
        while (lo < hi) { int m = (lo + hi) >> 1; if (yt[m] < xlo) lo = m + 1; else hi = m; }
        s_lo = lo;
        int lo2 = lo, hi2 = TY_;
        while (lo2 < hi2) { int m = (lo2 + hi2) >> 1; if (yt[m] <= xhi) lo2 = m + 1; else hi2 = m; }
        s_hi = lo2;
    }
    __syncthreads();

    const uint32_t qb = (uint32_t)__cvta_generic_to_shared(Qh);
    const uint32_t kb = (uint32_t)__cvta_generic_to_shared(Kh);
    const uint32_t vb = (uint32_t)__cvta_generic_to_shared(Vh);

    const uint32_t a_addr = qb + (uint32_t)(warp_q + (lane & 15)) * (QROW * 2)
                               + (uint32_t)(lane >> 4) * 16;
    const uint32_t key_off = ((lane >> 4) << 3) + (lane & 7);
    const uint32_t d_off = ((lane >> 3) & 1) << 3;
    const uint32_t k_addr = kb + key_off * (QROW * 2) + d_off * 2;
    const uint32_t v_addr = vb + (uint32_t)(lane & 15) * (QROW * 2)
                               + (uint32_t)(lane >> 4) * 16;

    float oacc[8][4];
#pragma unroll
    for (int j = 0; j < 8; j++)
#pragma unroll
        for (int e = 0; e < 4; e++) oacc[j][e] = 0.f;
    float m0 = -1e30f, m1 = -1e30f, l0 = 0.f, l1 = 0.f;

    const __half* kbase = g_kh + ((size_t)b * TY_) * C_ + h * D_;
    const __half* vbase = g_vh + ((size_t)b * TY_) * C_ + h * D_;

    const int kstart = s_lo & ~63;
    const int kend = s_hi;
    const float xti0 = sxt[warp_q + g] - fmind;
    const float xti1 = sxt[warp_q + g + 8] - fmind;

    for (int k0 = kstart; k0 < kend; k0 += 64) {
        __syncthreads();
        if (tid < 64) syt[tid] = yt[k0 + tid];
#pragma unroll
        for (int i = 0; i < 2; i++) {
            int idx = tid + i * 256;
            int row = idx >> 3, off = (idx & 7) * 8;
            size_t go = (size_t)(k0 + row) * C_ + off;
            *(uint4*)&Kh[row * QROW + off] = *(const uint4*)&kbase[go];
            *(uint4*)&Vh[row * QROW + off] = *(const uint4*)&vbase[go];
        }
        __syncthreads();

        // ---- S = Q K^T ----
        uint32_t af[4][4];
#pragma unroll
        for (int ks = 0; ks < 4; ks++)
            ldsm_x4(af[ks][0], af[ks][1], af[ks][2], af[ks][3], a_addr + ks * 32);

        float sacc[8][4];
#pragma unroll
        for (int j = 0; j < 8; j++)
#pragma unroll
            for (int e = 0; e < 4; e++) sacc[j][e] = 0.f;

#pragma unroll
        for (int ks = 0; ks < 4; ks++) {
#pragma unroll
            for (int p = 0; p < 4; p++) {
                uint32_t b0, b1, b2, b3;
                ldsm_x4(b0, b1, b2, b3, k_addr + (uint32_t)p * (16 * QROW * 2) + (uint32_t)ks * 32);
                uint32_t bf0[2] = {b0, b1}, bf1[2] = {b2, b3};
                mma_f16(sacc[2 * p], af[ks], bf0);
                mma_f16(sacc[2 * p + 1], af[ks], bf1);
            }
        }

        // ---- mask + online softmax ----
        float rmax0 = -1e30f, rmax1 = -1e30f;
#pragma unroll
        for (int j = 0; j < 8; j++) {
            float yt0 = syt[8 * j + 2 * t];
            float yt1 = syt[8 * j + 2 * t + 1];
            sacc[j][0] = (xti0 >= yt0 && xti0 <= yt0 + fdist) ? sacc[j][0] : -1e30f;
            sacc[j][1] = (xti0 >= yt1 && xti0 <= yt1 + fdist) ? sacc[j][1] : -1e30f;
            sacc[j][2] = (xti1 >= yt0 && xti1 <= yt0 + fdist) ? sacc[j][2] : -1e30f;
            sacc[j][3] = (xti1 >= yt1 && xti1 <= yt1 + fdist) ? sacc[j][3] : -1e30f;
            rmax0 = fmaxf(rmax0, fmaxf(sacc[j][0], sacc[j][1]));
            rmax1 = fmaxf(rmax1, fmaxf(sacc[j][2], sacc[j][3]));
        }
        rmax0 = fmaxf(rmax0, __shfl_xor_sync(0xffffffffu, rmax0, 1));
        rmax0 = fmaxf(rmax0, __shfl_xor_sync(0xffffffffu, rmax0, 2));
        rmax1 = fmaxf(rmax1, __shfl_xor_sync(0xffffffffu, rmax1, 1));
        rmax1 = fmaxf(rmax1, __shfl_xor_sync(0xffffffffu, rmax1, 2));

        const float mn0 = fmaxf(m0, rmax0);
        const float mn1 = fmaxf(m1, rmax1);
        const float alpha0 = __expf(m0 - mn0);
        const float alpha1 = __expf(m1 - mn1);
        m0 = mn0; m1 = mn1;

        float rs0 = 0.f, rs1 = 0.f;
#pragma unroll
        for (int j = 0; j < 8; j++) {
            float p0 = __expf(sacc[j][0] - mn0);
            float p1 = __expf(sacc[j][1] - mn0);
            float p2 = __expf(sacc[j][2] - mn1);
            float p3 = __expf(sacc[j][3] - mn1);
            sacc[j][0] = p0; sacc[j][1] = p1; sacc[j][2] = p2; sacc[j][3] = p3;
            rs0 += p0 + p1;
            rs1 += p2 + p3;
        }
        rs0 += __shfl_xor_sync(0xffffffffu, rs0, 1);
        rs0 += __shfl_xor_sync(0xffffffffu, rs0, 2);
        rs1 += __shfl_xor_sync(0xffffffffu, rs1, 1);
        rs1 += __shfl_xor_sync(0xffffffffu, rs1, 2);
        l0 = l0 * alpha0 + rs0;
        l1 = l1 * alpha1 + rs1;

#pragma unroll
        for (int j = 0; j < 8; j++) {
            oacc[j][0] *= alpha0; oacc[j][1] *= alpha0;
            oacc[j][2] *= alpha1; oacc[j][3] *= alpha1;
        }

        // ---- O += P @ V ----
#pragma unroll
        for (int ks = 0; ks < 4; ks++) {
            uint32_t pa[4];
            pa[0] = h2pack(sacc[2 * ks][0], sacc[2 * ks][1]);
            pa[1] = h2pack(sacc[2 * ks][2], sacc[2 * ks][3]);
            pa[2] = h2pack(sacc[2 * ks + 1][0], sacc[2 * ks + 1][1]);
            pa[3] = h2pack(sacc[2 * ks + 1][2], sacc[2 * ks + 1][3]);
#pragma unroll
            for (int p = 0; p < 4; p++) {
                uint32_t b0, b1, b2, b3;
                ldsm_x4_trans(b0, b1, b2, b3,
                              v_addr + (uint32_t)ks * (16 * QROW * 2) + (uint32_t)p * 32);
                uint32_t bf0[2] = {b0, b1}, bf1[2] = {b2, b3};
                mma_f16(oacc[2 * p], pa, bf0);
                mma_f16(oacc[2 * p + 1], pa, bf1);
            }
        }
    }

    // Epilogue: normalize, write fp32
    const float inv0 = 1.f / l0;
    const float inv1 = 1.f / l1;
    float* ob = g_o + ((size_t)(b * TX_ + q0 + warp_q)) * C_ + h * D_;
#pragma unroll
    for (int j = 0; j < 8; j++) {
        int col = 8 * j + 2 * t;
        *(float2*)&ob[(size_t)g * C_ + col] =
            make_float2(oacc[j][0] * inv0, oacc[j][1] * inv0);
        *(float2*)&ob[(size_t)(g + 8) * C_ + col] =
            make_float2(oacc[j][2] * inv1, oacc[j][3] * inv1);
    }
}

// ---------------------------------------------------------------------------
// Launch
// inputs: 0 x, 1 x_t, 2 y, 3 y_t, 4 dist, 5 min_dist, 6 Wq, 7 Wkv, 8 Wproj, 9 inv_freq
// ---------------------------------------------------------------------------
extern "C" void kernel_launch(void* const* d_in, const int* in_sizes, int n_in,
                              void* d_out, int out_size)
{
    const float* x        = (const float*)d_in[0];
    const float* x_t      = (const float*)d_in[1];
    const float* y        = (const float*)d_in[2];
    const float* y_t      = (const float*)d_in[3];
    const int*   dist     = (const int*)d_in[4];
    const int*   mind     = (const int*)d_in[5];
    const float* Wq       = (const float*)d_in[6];
    const float* Wkv      = (const float*)d_in[7];
    const float* Wproj    = (const float*)d_in[8];
    const float* inv_freq = (const float*)d_in[9];
    float* out = (float*)d_out;

    __half *qh_p, *kh_p, *vh_p;
    float *o_p;
    cudaGetSymbolAddress((void**)&qh_p, g_qh);
    cudaGetSymbolAddress((void**)&kh_p, g_kh);
    cudaGetSymbolAddress((void**)&vh_p, g_vh);
    cudaGetSymbolAddress((void**)&o_p, g_o);

    // fused: kv = y @ Wkv (rope k, split v) AND q = rope(x @ Wq) * 0.125
    gemm_qkv<<<KV_BLOCKS + Q_BLOCKS, 256>>>(
        x, Wq, y, Wkv, qh_p, kh_p, vh_p, x_t, y_t, inv_freq);
    // banded flash attention (fp16 tensor cores, 128-query tiles)
    attn_tc<<<dim3(TX_ / 128, H_, B_), 256>>>(x_t, y_t, dist, mind);
    // final projection: out = o @ Wproj (fp32 out)
    gemm_proj<<<dim3(C_ / 64, (B_ * TX_) / 128), 256>>>(o_p, Wproj, out, C_, C_);
}

// round 17
// speedup vs baseline: 1.6248x; 1.0188x over previous
#include <cuda_runtime.h>
#include <cuda_fp16.h>
#include <math.h>
#include <stdint.h>

// Problem constants
#define B_   2
#define TX_  1024
#define TY_  4096
#define C_   768
#define H_   12
#define D_   64

// Scratch (device globals: no allocation allowed)
__device__ __half g_qh[B_ * TX_ * C_];   // rope(q) * 0.125, fp16
__device__ __half g_kh[B_ * TY_ * C_];   // rope(k), fp16
__device__ __half g_vh[B_ * TY_ * C_];   // v, fp16
__device__ float  g_o [B_ * TX_ * C_];   // attention output, fp32
__device__ __half g_wqh [C_ * C_];       // Wq fp16
__device__ __half g_wkvh[C_ * 2 * C_];   // Wkv fp16
__device__ __half g_wph [C_ * C_];       // Wproj fp16

// ---------------------------------------------------------------------------
// mma / ldmatrix helpers (sm_80-era instructions, valid on base sm_103)
// ---------------------------------------------------------------------------
__device__ __forceinline__ void mma_f16(float* d, const uint32_t* a, const uint32_t* b) {
    asm volatile(
        "mma.sync.aligned.m16n8k16.row.col.f32.f16.f16.f32 "
        "{%0,%1,%2,%3}, {%4,%5,%6,%7}, {%8,%9}, {%0,%1,%2,%3};"
        : "+f"(d[0]), "+f"(d[1]), "+f"(d[2]), "+f"(d[3])
        : "r"(a[0]), "r"(a[1]), "r"(a[2]), "r"(a[3]), "r"(b[0]), "r"(b[1]));
}

__device__ __forceinline__ void ldsm_x4(uint32_t& r0, uint32_t& r1, uint32_t& r2,
                                        uint32_t& r3, uint32_t addr) {
    asm volatile("ldmatrix.sync.aligned.m8n8.x4.shared.b16 {%0,%1,%2,%3}, [%4];"
                 : "=r"(r0), "=r"(r1), "=r"(r2), "=r"(r3) : "r"(addr));
}

__device__ __forceinline__ void ldsm_x4_trans(uint32_t& r0, uint32_t& r1, uint32_t& r2,
                                              uint32_t& r3, uint32_t addr) {
    asm volatile("ldmatrix.sync.aligned.m8n8.x4.trans.shared.b16 {%0,%1,%2,%3}, [%4];"
                 : "=r"(r0), "=r"(r1), "=r"(r2), "=r"(r3) : "r"(addr));
}

__device__ __forceinline__ uint32_t h2pack(float a, float b) {
    __half2 h = __floats2half2_rn(a, b);
    return *(uint32_t*)&h;
}

// ---------------------------------------------------------------------------
// fp32 -> fp16 weight prepass (n multiple of 1024)
// ---------------------------------------------------------------------------
__global__ __launch_bounds__(256) void cvt_kernel(
    const float* __restrict__ src, __half* __restrict__ dst, int n)
{
    int i = (blockIdx.x * 256 + threadIdx.x) * 4;
    if (i < n) {
        float4 v = *(const float4*)&src[i];
        __half2* d = (__half2*)&dst[i];
        d[0] = __floats2half2_rn(v.x, v.y);
        d[1] = __floats2half2_rn(v.z, v.w);
    }
}

// ---------------------------------------------------------------------------
// GEMM body, block tile 128x64, 256 threads, 2 CTAs/SM, double-buffered smem.
// A fp32 (converted inline), W fp16 (pre-converted, raw uint4 copies).
// 8 warps = 4m x 2n, warp tile 32x32. Register-staged prefetch.
// mode 0: fp32 output to out0 (width N).
// mode 1: RoPE(pos) + *0.125 -> fp16 to out0 (width N). (Q path)
// mode 2: cols [0,splitN): RoPE(pos) -> fp16 out0; cols [splitN,N): fp16 out1.
// ---------------------------------------------------------------------------
#define AROW 40     // 32 + 8 pad (halfs)
#define BROWS 72    // 64 + 8 pad (halfs)
#define A_ST (128 * AROW)
#define B_ST (32 * BROWS)

__device__ __forceinline__ void gemm_body(
    const float* __restrict__ A, const __half* __restrict__ W,
    void* __restrict__ out0v, void* __restrict__ out1v,
    int N, int K, int splitN, int mode,
    const float* __restrict__ pos, const float* __restrict__ invf,
    int bn, int bm)
{
    __shared__ __half Asm[2][A_ST];   // [m][k]
    __shared__ __half Bsm[2][B_ST];   // [k][n]
    __shared__ float spos[128];
    __shared__ float sif[32];

    const int tid = threadIdx.x;
    const int wid = tid >> 5, lane = tid & 31;
    const int g = lane >> 2, t = lane & 3;
    const int warp_m = (wid >> 1) * 32;   // 0,32,64,96
    const int warp_n = (wid & 1) * 32;    // 0,32

    if (mode != 0) {
        if (tid < 128) spos[tid] = pos[bm + tid];
        if (tid < 32) sif[tid] = invf[tid];
    }

    float acc[2][4][4];
#pragma unroll
    for (int mt = 0; mt < 2; mt++)
#pragma unroll
        for (int nt = 0; nt < 4; nt++)
#pragma unroll
            for (int e = 0; e < 4; e++) acc[mt][nt][e] = 0.f;

    const uint32_t a_base = (uint32_t)__cvta_generic_to_shared(&Asm[0][0]);
    const uint32_t b_base = (uint32_t)__cvta_generic_to_shared(&Bsm[0][0]);

    const uint32_t a_frag0 = (uint32_t)(warp_m + (lane & 15)) * (AROW * 2)
                           + (uint32_t)(lane >> 4) * 16;
    const uint32_t b_frag0 = (uint32_t)(lane & 15) * (BROWS * 2)
                           + (uint32_t)(warp_n + (lane >> 4) * 8) * 2;

    // per-thread fill coordinates: A 4 float4 loads, B 1 uint4 copy
    const int a_row = tid >> 3, a_c4 = (tid & 7) * 4;     // +32 rows per i
    const int b_row = tid >> 3, b_seg = (tid & 7) * 8;    // 32 rows x 8 segs

    float4 pa[4];
    uint4 pb;

    // prefetch + store chunk 0 into buffer 0
#pragma unroll
    for (int i = 0; i < 4; i++)
        pa[i] = *(const float4*)&A[(size_t)(bm + a_row + i * 32) * K + a_c4];
    pb = *(const uint4*)&W[(size_t)b_row * N + bn + b_seg];
#pragma unroll
    for (int i = 0; i < 4; i++) {
        __half2* da = (__half2*)&Asm[0][(a_row + i * 32) * AROW + a_c4];
        da[0] = __floats2half2_rn(pa[i].x, pa[i].y);
        da[1] = __floats2half2_rn(pa[i].z, pa[i].w);
    }
    *(uint4*)&Bsm[0][b_row * BROWS + b_seg] = pb;
    __syncthreads();

    const int nch = K / 32;
    for (int c = 0; c < nch; c++) {
        // issue next chunk's global loads (overlap with MMAs below)
        if (c + 1 < nch) {
            const int k0 = (c + 1) * 32;
#pragma unroll
            for (int i = 0; i < 4; i++)
                pa[i] = *(const float4*)&A[(size_t)(bm + a_row + i * 32) * K + k0 + a_c4];
            pb = *(const uint4*)&W[(size_t)(k0 + b_row) * N + bn + b_seg];
        }

        // compute chunk c from buffer c&1
        const uint32_t a_addr = a_base + (uint32_t)(c & 1) * (A_ST * 2) + a_frag0;
        const uint32_t b_addr = b_base + (uint32_t)(c & 1) * (B_ST * 2) + b_frag0;
#pragma unroll
        for (int kk16 = 0; kk16 < 32; kk16 += 16) {
            uint32_t af[2][4];
            ldsm_x4(af[0][0], af[0][1], af[0][2], af[0][3], a_addr + kk16 * 2);
            ldsm_x4(af[1][0], af[1][1], af[1][2], af[1][3],
                    a_addr + 16 * (AROW * 2) + kk16 * 2);

            uint32_t bf[4][2];
#pragma unroll
            for (int p = 0; p < 2; p++) {
                ldsm_x4_trans(bf[2 * p][0], bf[2 * p][1], bf[2 * p + 1][0], bf[2 * p + 1][1],
                              b_addr + (uint32_t)kk16 * (BROWS * 2) + (uint32_t)p * 32);
            }
#pragma unroll
            for (int nt = 0; nt < 4; nt++) {
#pragma unroll
                for (int mt = 0; mt < 2; mt++)
                    mma_f16(acc[mt][nt], af[mt], bf[nt]);
            }
        }

        // store next chunk into the other buffer (no readers there this iter)
        if (c + 1 < nch) {
            const int s = (c + 1) & 1;
#pragma unroll
            for (int i = 0; i < 4; i++) {
                __half2* da = (__half2*)&Asm[s][(a_row + i * 32) * AROW + a_c4];
                da[0] = __floats2half2_rn(pa[i].x, pa[i].y);
                da[1] = __floats2half2_rn(pa[i].z, pa[i].w);
            }
            *(uint4*)&Bsm[s][b_row * BROWS + b_seg] = pb;
        }
        __syncthreads();
    }

    if (mode == 0) {
        float* dst = (float*)out0v;
#pragma unroll
        for (int mt = 0; mt < 2; mt++) {
#pragma unroll
            for (int nt = 0; nt < 4; nt++) {
                int row = bm + warp_m + mt * 16 + g;
                int col = bn + warp_n + nt * 8 + t * 2;
                *(float2*)&dst[(size_t)row * N + col] =
                    make_float2(acc[mt][nt][0], acc[mt][nt][1]);
                *(float2*)&dst[(size_t)(row + 8) * N + col] =
                    make_float2(acc[mt][nt][2], acc[mt][nt][3]);
            }
        }
    } else {
        const bool is_v = (mode == 2) && (bn >= splitN);
        __half* dsth;
        int col0, stride;
        if (mode == 1)      { dsth = (__half*)out0v; col0 = bn; stride = N; }
        else if (!is_v)     { dsth = (__half*)out0v; col0 = bn; stride = splitN; }
        else                { dsth = (__half*)out1v; col0 = bn - splitN; stride = N - splitN; }
        const float scale = (mode == 1) ? 0.125f : 1.0f;

#pragma unroll
        for (int mt = 0; mt < 2; mt++) {
            const int r0 = warp_m + mt * 16 + g;
            const float p0 = spos[r0], p1 = spos[r0 + 8];
#pragma unroll
            for (int nt = 0; nt < 4; nt++) {
                int col = col0 + warp_n + nt * 8 + t * 2;
                float e0 = acc[mt][nt][0], o0 = acc[mt][nt][1];
                float e1 = acc[mt][nt][2], o1 = acc[mt][nt][3];
                if (!is_v) {
                    const float fr = sif[(col & 63) >> 1];
                    float s, cc;
                    sincosf(p0 * fr, &s, &cc);
                    float te = e0 * cc - o0 * s, to = o0 * cc + e0 * s;
                    sincosf(p1 * fr, &s, &cc);
                    float te1 = e1 * cc - o1 * s, to1 = o1 * cc + e1 * s;
                    e0 = te * scale; o0 = to * scale;
                    e1 = te1 * scale; o1 = to1 * scale;
                }
                *(__half2*)&dsth[(size_t)(bm + r0) * stride + col] = __floats2half2_rn(e0, o0);
                *(__half2*)&dsth[(size_t)(bm + r0 + 8) * stride + col] = __floats2half2_rn(e1, o1);
            }
        }
    }
}

// Fused Q + KV projection with 128x64 tiles:
// KV: 24 N-tiles x 64 M-tiles = 1536 blocks; Q: 12 x 16 = 192 blocks.
#define KV_BLOCKS (24 * 64)
#define Q_BLOCKS  (12 * 16)

__global__ __launch_bounds__(256, 2) void gemm_qkv(
    const float* __restrict__ x, const __half* __restrict__ Wq,
    const float* __restrict__ y, const __half* __restrict__ Wkv,
    __half* __restrict__ qh, __half* __restrict__ kh, __half* __restrict__ vh,
    const float* __restrict__ x_t, const float* __restrict__ y_t,
    const float* __restrict__ invf)
{
    const int bid = blockIdx.x;
    if (bid < KV_BLOCKS) {
        int bn = (bid % 24) * 64, bm = (bid / 24) * 128;
        gemm_body(y, Wkv, kh, vh, 2 * C_, C_, C_, 2, y_t, invf, bn, bm);
    } else {
        int r = bid - KV_BLOCKS;
        int bn = (r % 12) * 64, bm = (r / 12) * 128;
        gemm_body(x, Wq, qh, nullptr, C_, C_, 0, 1, x_t, invf, bn, bm);
    }
}

// Standalone gemm for the output projection (mode 0, fp32 out).
__global__ __launch_bounds__(256, 2) void gemm_proj(
    const float* __restrict__ A, const __half* __restrict__ W,
    float* __restrict__ out, int N, int K)
{
    gemm_body(A, W, out, nullptr, N, K, 0, 0, nullptr, nullptr,
              blockIdx.x * 64, blockIdx.y * 128);
}

// ---------------------------------------------------------------------------
// Banded flash-attention, fp16 tensor cores, fp32 accumulate + softmax.
// Block = (b, h, 128-query tile), 256 threads = 8 warps, warp handles m16.
// (identical to the 209.4us R15 kernel)
// ---------------------------------------------------------------------------
#define QROW 72   // halfs per smem row (64 + 8 pad, 144B)

__global__ __launch_bounds__(256) void attn_tc(
    const float* __restrict__ xt_g, const float* __restrict__ yt_g,
    const int* __restrict__ p_dist, const int* __restrict__ p_mind)
{
    __shared__ __align__(16) __half Qh[128 * QROW];
    __shared__ __align__(16) __half Kh[64 * QROW];
    __shared__ __align__(16) __half Vh[64 * QROW];
    __shared__ float sxt[128], syt[64];
    __shared__ int s_lo, s_hi;

    const int b = blockIdx.z, h = blockIdx.y, q0 = blockIdx.x * 128;
    const int tid = threadIdx.x;
    const int wid = tid >> 5, lane = tid & 31;
    const int g = lane >> 2, t = lane & 3;
    const int warp_q = wid * 16;

    const float fdist = (float)p_dist[0];
    const float fmind = (float)p_mind[0];
    const float* yt = yt_g + (size_t)b * TY_;

    const __half* qbase = g_qh + ((size_t)(b * TX_ + q0)) * C_ + h * D_;
#pragma unroll
    for (int i = 0; i < 4; i++) {
        int idx = tid + i * 256;
        int row = idx >> 3, off = (idx & 7) * 8;
        *(uint4*)&Qh[row * QROW + off] = *(const uint4*)&qbase[(size_t)row * C_ + off];
    }
    if (tid < 128) sxt[tid] = xt_g[b * TX_ + q0 + tid];

    if (tid == 0) {
        float xlo = xt_g[b * TX_ + q0] - fmind - fdist;
        float xhi = xt_g[b * TX_ + q0 + 127] - fmind;
        int lo = 0, hi = TY_;
        while (lo < hi) { int m = (lo + hi) >> 1; if (yt[m] < xlo) lo = m + 1; else hi = m; }
        s_lo = lo;
        int lo2 = lo, hi2 = TY_;
        while (lo2 < hi2) { int m = (lo2 + hi2) >> 1; if (yt[m] <= xhi) lo2 = m + 1; else hi2 = m; }
        s_hi = lo2;
    }
    __syncthreads();

    const uint32_t qb = (uint32_t)__cvta_generic_to_shared(Qh);
    const uint32_t kb = (uint32_t)__cvta_generic_to_shared(Kh);
    const uint32_t vb = (uint32_t)__cvta_generic_to_shared(Vh);

    const uint32_t a_addr = qb + (uint32_t)(warp_q + (lane & 15)) * (QROW * 2)
                               + (uint32_t)(lane >> 4) * 16;
    const uint32_t key_off = ((lane >> 4) << 3) + (lane & 7);
    const uint32_t d_off = ((lane >> 3) & 1) << 3;
    const uint32_t k_addr = kb + key_off * (QROW * 2) + d_off * 2;
    const uint32_t v_addr = vb + (uint32_t)(lane & 15) * (QROW * 2)
                               + (uint32_t)(lane >> 4) * 16;

    float oacc[8][4];
#pragma unroll
    for (int j = 0; j < 8; j++)
#pragma unroll
        for (int e = 0; e < 4; e++) oacc[j][e] = 0.f;
    float m0 = -1e30f, m1 = -1e30f, l0 = 0.f, l1 = 0.f;

    const __half* kbase = g_kh + ((size_t)b * TY_) * C_ + h * D_;
    const __half* vbase = g_vh + ((size_t)b * TY_) * C_ + h * D_;

    const int kstart = s_lo & ~63;
    const int kend = s_hi;
    const float xti0 = sxt[warp_q + g] - fmind;
    const float xti1 = sxt[warp_q + g + 8] - fmind;

    for (int k0 = kstart; k0 < kend; k0 += 64) {
        __syncthreads();
        if (tid < 64) syt[tid] = yt[k0 + tid];
#pragma unroll
        for (int i = 0; i < 2; i++) {
            int idx = tid + i * 256;
            int row = idx >> 3, off = (idx & 7) * 8;
            size_t go = (size_t)(k0 + row) * C_ + off;
            *(uint4*)&Kh[row * QROW + off] = *(const uint4*)&kbase[go];
            *(uint4*)&Vh[row * QROW + off] = *(const uint4*)&vbase[go];
        }
        __syncthreads();

        // ---- S = Q K^T ----
        uint32_t af[4][4];
#pragma unroll
        for (int ks = 0; ks < 4; ks++)
            ldsm_x4(af[ks][0], af[ks][1], af[ks][2], af[ks][3], a_addr + ks * 32);

        float sacc[8][4];
#pragma unroll
        for (int j = 0; j < 8; j++)
#pragma unroll
            for (int e = 0; e < 4; e++) sacc[j][e] = 0.f;

#pragma unroll
        for (int ks = 0; ks < 4; ks++) {
#pragma unroll
            for (int p = 0; p < 4; p++) {
                uint32_t b0, b1, b2, b3;
                ldsm_x4(b0, b1, b2, b3, k_addr + (uint32_t)p * (16 * QROW * 2) + (uint32_t)ks * 32);
                uint32_t bf0[2] = {b0, b1}, bf1[2] = {b2, b3};
                mma_f16(sacc[2 * p], af[ks], bf0);
                mma_f16(sacc[2 * p + 1], af[ks], bf1);
            }
        }

        // ---- mask + online softmax ----
        float rmax0 = -1e30f, rmax1 = -1e30f;
#pragma unroll
        for (int j = 0; j < 8; j++) {
            float yt0 = syt[8 * j + 2 * t];
            float yt1 = syt[8 * j + 2 * t + 1];
            sacc[j][0] = (xti0 >= yt0 && xti0 <= yt0 + fdist) ? sacc[j][0] : -1e30f;
            sacc[j][1] = (xti0 >= yt1 && xti0 <= yt1 + fdist) ? sacc[j][1] : -1e30f;
            sacc[j][2] = (xti1 >= yt0 && xti1 <= yt0 + fdist) ? sacc[j][2] : -1e30f;
            sacc[j][3] = (xti1 >= yt1 && xti1 <= yt1 + fdist) ? sacc[j][3] : -1e30f;
            rmax0 = fmaxf(rmax0, fmaxf(sacc[j][0], sacc[j][1]));
            rmax1 = fmaxf(rmax1, fmaxf(sacc[j][2], sacc[j][3]));
        }
        rmax0 = fmaxf(rmax0, __shfl_xor_sync(0xffffffffu, rmax0, 1));
        rmax0 = fmaxf(rmax0, __shfl_xor_sync(0xffffffffu, rmax0, 2));
        rmax1 = fmaxf(rmax1, __shfl_xor_sync(0xffffffffu, rmax1, 1));
        rmax1 = fmaxf(rmax1, __shfl_xor_sync(0xffffffffu, rmax1, 2));

        const float mn0 = fmaxf(m0, rmax0);
        const float mn1 = fmaxf(m1, rmax1);
        const float alpha0 = __expf(m0 - mn0);
        const float alpha1 = __expf(m1 - mn1);
        m0 = mn0; m1 = mn1;

        float rs0 = 0.f, rs1 = 0.f;
#pragma unroll
        for (int j = 0; j < 8; j++) {
            float p0 = __expf(sacc[j][0] - mn0);
            float p1 = __expf(sacc[j][1] - mn0);
            float p2 = __expf(sacc[j][2] - mn1);
            float p3 = __expf(sacc[j][3] - mn1);
            sacc[j][0] = p0; sacc[j][1] = p1; sacc[j][2] = p2; sacc[j][3] = p3;
            rs0 += p0 + p1;
            rs1 += p2 + p3;
        }
        rs0 += __shfl_xor_sync(0xffffffffu, rs0, 1);
        rs0 += __shfl_xor_sync(0xffffffffu, rs0, 2);
        rs1 += __shfl_xor_sync(0xffffffffu, rs1, 1);
        rs1 += __shfl_xor_sync(0xffffffffu, rs1, 2);
        l0 = l0 * alpha0 + rs0;
        l1 = l1 * alpha1 + rs1;

#pragma unroll
        for (int j = 0; j < 8; j++) {
            oacc[j][0] *= alpha0; oacc[j][1] *= alpha0;
            oacc[j][2] *= alpha1; oacc[j][3] *= alpha1;
        }

        // ---- O += P @ V ----
#pragma unroll
        for (int ks = 0; ks < 4; ks++) {
            uint32_t pa[4];
            pa[0] = h2pack(sacc[2 * ks][0], sacc[2 * ks][1]);
            pa[1] = h2pack(sacc[2 * ks][2], sacc[2 * ks][3]);
            pa[2] = h2pack(sacc[2 * ks + 1][0], sacc[2 * ks + 1][1]);
            pa[3] = h2pack(sacc[2 * ks + 1][2], sacc[2 * ks + 1][3]);
#pragma unroll
            for (int p = 0; p < 4; p++) {
                uint32_t b0, b1, b2, b3;
                ldsm_x4_trans(b0, b1, b2, b3,
                              v_addr + (uint32_t)ks * (16 * QROW * 2) + (uint32_t)p * 32);
                uint32_t bf0[2] = {b0, b1}, bf1[2] = {b2, b3};
                mma_f16(oacc[2 * p], pa, bf0);
                mma_f16(oacc[2 * p + 1], pa, bf1);
            }
        }
    }

    // Epilogue: normalize, write fp32
    const float inv0 = 1.f / l0;
    const float inv1 = 1.f / l1;
    float* ob = g_o + ((size_t)(b * TX_ + q0 + warp_q)) * C_ + h * D_;
#pragma unroll
    for (int j = 0; j < 8; j++) {
        int col = 8 * j + 2 * t;
        *(float2*)&ob[(size_t)g * C_ + col] =
            make_float2(oacc[j][0] * inv0, oacc[j][1] * inv0);
        *(float2*)&ob[(size_t)(g + 8) * C_ + col] =
            make_float2(oacc[j][2] * inv1, oacc[j][3] * inv1);
    }
}

// ---------------------------------------------------------------------------
// Launch
// inputs: 0 x, 1 x_t, 2 y, 3 y_t, 4 dist, 5 min_dist, 6 Wq, 7 Wkv, 8 Wproj, 9 inv_freq
// ---------------------------------------------------------------------------
extern "C" void kernel_launch(void* const* d_in, const int* in_sizes, int n_in,
                              void* d_out, int out_size)
{
    const float* x        = (const float*)d_in[0];
    const float* x_t      = (const float*)d_in[1];
    const float* y        = (const float*)d_in[2];
    const float* y_t      = (const float*)d_in[3];
    const int*   dist     = (const int*)d_in[4];
    const int*   mind     = (const int*)d_in[5];
    const float* Wq       = (const float*)d_in[6];
    const float* Wkv      = (const float*)d_in[7];
    const float* Wproj    = (const float*)d_in[8];
    const float* inv_freq = (const float*)d_in[9];
    float* out = (float*)d_out;

    __half *qh_p, *kh_p, *vh_p, *wqh_p, *wkvh_p, *wph_p;
    float *o_p;
    cudaGetSymbolAddress((void**)&qh_p, g_qh);
    cudaGetSymbolAddress((void**)&kh_p, g_kh);
    cudaGetSymbolAddress((void**)&vh_p, g_vh);
    cudaGetSymbolAddress((void**)&o_p, g_o);
    cudaGetSymbolAddress((void**)&wqh_p, g_wqh);
    cudaGetSymbolAddress((void**)&wkvh_p, g_wkvh);
    cudaGetSymbolAddress((void**)&wph_p, g_wph);

    // weight fp16 prepass (9 MB total)
    const int nwq = C_ * C_, nwkv = C_ * 2 * C_;
    cvt_kernel<<<nwq / 1024, 256>>>(Wq, wqh_p, nwq);
    cvt_kernel<<<nwkv / 1024, 256>>>(Wkv, wkvh_p, nwkv);
    cvt_kernel<<<nwq / 1024, 256>>>(Wproj, wph_p, nwq);

    // fused: kv = y @ Wkv (rope k, split v) AND q = rope(x @ Wq) * 0.125
    gemm_qkv<<<KV_BLOCKS + Q_BLOCKS, 256>>>(
        x, wqh_p, y, wkvh_p, qh_p, kh_p, vh_p, x_t, y_t, inv_freq);
    // banded flash attention (fp16 tensor cores, 128-query tiles)
    attn_tc<<<dim3(TX_ / 128, H_, B_), 256>>>(x_t, y_t, dist, mind);
    // final projection: out = o @ Wproj (fp32 out)
    gemm_proj<<<dim3(C_ / 64, (B_ * TX_) / 128), 256>>>(o_p, wph_p, out, C_, C_);
}